// round 1
// baseline (speedup 1.0000x reference)
#include <cuda_runtime.h>

#define NN  50000
#define D   128
#define KNB 16
#define WS  132   // padded smem stride for transposed weights (conflict-free float4 reads)

// Scratch for the two projections (static device arrays: allocation rules forbid cudaMalloc)
__device__ float g_eh[(size_t)NN * D];
__device__ float g_et[(size_t)NN * D];

__device__ __forceinline__ float tanh_fast(float z) {
    z = fminf(15.0f, fmaxf(-15.0f, z));
    float e = __expf(2.0f * z);
    return __fdividef(e - 1.0f, e + 1.0f);
}

// ---------------------------------------------------------------------------
// Kernel A: e_h = eh_in @ Wh^T + bh  (blockIdx.y==0)
//           e_t = et_in @ Wt^T + bt  (blockIdx.y==1)
// 64 rows/block, 256 threads, 8 rows x 4 cols per thread.
// ---------------------------------------------------------------------------
__global__ void __launch_bounds__(256) proj_kernel(
    const float* __restrict__ eh_in, const float* __restrict__ et_in,
    const float* __restrict__ Wh, const float* __restrict__ bh,
    const float* __restrict__ Wt, const float* __restrict__ bt)
{
    extern __shared__ float sm[];
    float* Wsh = sm;               // D * WS (transposed: Wsh[k][c] = W[c][k])
    float* Xsh = sm + D * WS;      // 64 * D

    const float *in, *W, *b;
    float* out;
    if (blockIdx.y == 0) { in = eh_in; W = Wh; b = bh; out = g_eh; }
    else                 { in = et_in; W = Wt; b = bt; out = g_et; }

    const int tid = threadIdx.x;
    const int n0  = blockIdx.x * 64;

    for (int i = tid; i < D * D; i += 256) {
        int c = i >> 7, k = i & 127;
        Wsh[k * WS + c] = W[i];
    }
    const float4* in4 = (const float4*)in;
    float4* Xsh4 = (float4*)Xsh;
    for (int i = tid; i < 64 * 32; i += 256) {
        int r = i >> 5, s = i & 31;
        int n = n0 + r;
        float4 v = make_float4(0.f, 0.f, 0.f, 0.f);
        if (n < NN) v = in4[n * 32 + s];
        Xsh4[i] = v;
    }
    __syncthreads();

    const int lane = tid & 31;
    const int rg   = tid >> 5;     // 0..7 : row group of 8
    const int c0   = lane << 2;    // 4 consecutive output cols

    float acc[8][4];
    #pragma unroll
    for (int r = 0; r < 8; r++) {
        acc[r][0] = 0.f; acc[r][1] = 0.f; acc[r][2] = 0.f; acc[r][3] = 0.f;
    }

    const float* xb = Xsh + rg * 8 * D;
    #pragma unroll 4
    for (int k = 0; k < D; k++) {
        float4 w = *(const float4*)&Wsh[k * WS + c0];
        #pragma unroll
        for (int r = 0; r < 8; r++) {
            float xv = xb[r * D + k];
            acc[r][0] = fmaf(xv, w.x, acc[r][0]);
            acc[r][1] = fmaf(xv, w.y, acc[r][1]);
            acc[r][2] = fmaf(xv, w.z, acc[r][2]);
            acc[r][3] = fmaf(xv, w.w, acc[r][3]);
        }
    }

    float4 bv = *(const float4*)&b[c0];
    #pragma unroll
    for (int r = 0; r < 8; r++) {
        int n = n0 + rg * 8 + r;
        if (n < NN) {
            float4 o = make_float4(acc[r][0] + bv.x, acc[r][1] + bv.y,
                                   acc[r][2] + bv.z, acc[r][3] + bv.w);
            ((float4*)out)[n * 32 + lane] = o;
        }
    }
}

// ---------------------------------------------------------------------------
// Kernel B: fused attention + final two GEMMs + layernorm.
// 64 rows/block, 512 threads (16 warps). Attention: 1 warp per row (4 rows
// sequentially per warp, neighbors kept in registers). GEMM: 4 rows x 4 cols
// x 2 matrices per thread. Layernorm via warp shuffles (each row lives in one
// warp: lane holds cols 4*lane..4*lane+3).
// ---------------------------------------------------------------------------
__global__ void __launch_bounds__(512, 1) fused_kernel(
    const float* __restrict__ x, const int* __restrict__ tidx,
    const float* __restrict__ tw,
    const float* __restrict__ W1, const float* __restrict__ b1,
    const float* __restrict__ W2, const float* __restrict__ b2,
    const float* __restrict__ gamma, const float* __restrict__ beta,
    float* __restrict__ out)
{
    extern __shared__ float sm[];
    float* W1sh = sm;                    // D * WS
    float* W2sh = sm + D * WS;           // D * WS
    float* Ush  = sm + 2 * D * WS;       // 64 * D
    float* Vsh  = Ush + 64 * D;          // 64 * D

    const int tid  = threadIdx.x;
    const int lane = tid & 31;
    const int warp = tid >> 5;           // 0..15
    const int n0   = blockIdx.x * 64;

    for (int i = tid; i < D * D; i += 512) {
        int c = i >> 7, k = i & 127;
        W1sh[k * WS + c] = W1[i];
        W2sh[k * WS + c] = W2[i];
    }

    // ---- attention phase: warp handles rows warp*4 .. warp*4+3 ----
    for (int rr = 0; rr < 4; rr++) {
        const int rloc = warp * 4 + rr;
        const int n = n0 + rloc;
        float4 u = make_float4(0.f, 0.f, 0.f, 0.f);
        float4 v = make_float4(0.f, 0.f, 0.f, 0.f);
        if (n < NN) {
            float4 eh = ((const float4*)g_eh)[n * 32 + lane];
            float4 xr = ((const float4*)x)[n * 32 + lane];
            float nb[KNB][4];
            float lg[KNB];
            #pragma unroll
            for (int k = 0; k < KNB; k++) {
                int   id = tidx[n * KNB + k];
                float p  = tw[n * KNB + k];
                float4 nv = ((const float4*)g_et)[id * 32 + lane];
                nb[k][0] = nv.x; nb[k][1] = nv.y; nb[k][2] = nv.z; nb[k][3] = nv.w;
                float q = 2.0f - p;
                // gate arg: e_h + (p*Nb + (1-p)*e_h) = (2-p)*e_h + p*Nb
                float part;
                part  = nv.x * tanh_fast(fmaf(q, eh.x, p * nv.x));
                part += nv.y * tanh_fast(fmaf(q, eh.y, p * nv.y));
                part += nv.z * tanh_fast(fmaf(q, eh.z, p * nv.z));
                part += nv.w * tanh_fast(fmaf(q, eh.w, p * nv.w));
                #pragma unroll
                for (int o = 16; o >= 1; o >>= 1)
                    part += __shfl_xor_sync(0xffffffffu, part, o);
                lg[k] = part;   // full logit, replicated on all lanes
            }
            // softmax over 16 (replicated per-lane)
            float m = lg[0];
            #pragma unroll
            for (int k = 1; k < KNB; k++) m = fmaxf(m, lg[k]);
            float s = 0.f;
            #pragma unroll
            for (int k = 0; k < KNB; k++) { lg[k] = __expf(lg[k] - m); s += lg[k]; }
            float inv = __fdividef(1.0f, s);
            float e0 = 0.f, e1 = 0.f, e2 = 0.f, e3 = 0.f;
            #pragma unroll
            for (int k = 0; k < KNB; k++) {
                float pr = lg[k] * inv;
                e0 = fmaf(pr, nb[k][0], e0);
                e1 = fmaf(pr, nb[k][1], e1);
                e2 = fmaf(pr, nb[k][2], e2);
                e3 = fmaf(pr, nb[k][3], e3);
            }
            u = make_float4(xr.x + e0, xr.y + e1, xr.z + e2, xr.w + e3);
            v = make_float4(xr.x * e0, xr.y * e1, xr.z * e2, xr.w * e3);
        }
        ((float4*)(Ush + rloc * D))[lane] = u;
        ((float4*)(Vsh + rloc * D))[lane] = v;
    }
    __syncthreads();

    // ---- GEMM phase: h = leaky(u@W1^T+b1) + leaky(v@W2^T+b2) ----
    const int c0 = lane << 2;
    float a1[4][4], a2[4][4];
    #pragma unroll
    for (int r = 0; r < 4; r++) {
        a1[r][0]=0.f; a1[r][1]=0.f; a1[r][2]=0.f; a1[r][3]=0.f;
        a2[r][0]=0.f; a2[r][1]=0.f; a2[r][2]=0.f; a2[r][3]=0.f;
    }
    const float* ub = Ush + warp * 4 * D;
    const float* vb = Vsh + warp * 4 * D;
    #pragma unroll 2
    for (int k = 0; k < D; k++) {
        float4 w1 = *(const float4*)&W1sh[k * WS + c0];
        float4 w2 = *(const float4*)&W2sh[k * WS + c0];
        #pragma unroll
        for (int r = 0; r < 4; r++) {
            float uk = ub[r * D + k];
            float vk = vb[r * D + k];
            a1[r][0] = fmaf(uk, w1.x, a1[r][0]);
            a1[r][1] = fmaf(uk, w1.y, a1[r][1]);
            a1[r][2] = fmaf(uk, w1.z, a1[r][2]);
            a1[r][3] = fmaf(uk, w1.w, a1[r][3]);
            a2[r][0] = fmaf(vk, w2.x, a2[r][0]);
            a2[r][1] = fmaf(vk, w2.y, a2[r][1]);
            a2[r][2] = fmaf(vk, w2.z, a2[r][2]);
            a2[r][3] = fmaf(vk, w2.w, a2[r][3]);
        }
    }

    float4 b1v = *(const float4*)&b1[c0];
    float4 b2v = *(const float4*)&b2[c0];
    float4 gv  = *(const float4*)&gamma[c0];
    float4 bev = *(const float4*)&beta[c0];
    float b1a[4] = {b1v.x, b1v.y, b1v.z, b1v.w};
    float b2a[4] = {b2v.x, b2v.y, b2v.z, b2v.w};
    float ga[4]  = {gv.x, gv.y, gv.z, gv.w};
    float ba[4]  = {bev.x, bev.y, bev.z, bev.w};

    #pragma unroll
    for (int r = 0; r < 4; r++) {
        int n = n0 + warp * 4 + r;
        float h[4];
        #pragma unroll
        for (int j = 0; j < 4; j++) {
            float t1 = a1[r][j] + b1a[j];
            t1 = (t1 > 0.f) ? t1 : 0.01f * t1;
            float t2 = a2[r][j] + b2a[j];
            t2 = (t2 > 0.f) ? t2 : 0.01f * t2;
            h[j] = t1 + t2;
        }
        float s  = h[0] + h[1] + h[2] + h[3];
        float sq = h[0]*h[0] + h[1]*h[1] + h[2]*h[2] + h[3]*h[3];
        #pragma unroll
        for (int o = 16; o >= 1; o >>= 1) {
            s  += __shfl_xor_sync(0xffffffffu, s,  o);
            sq += __shfl_xor_sync(0xffffffffu, sq, o);
        }
        float mu  = s * (1.0f / 128.0f);
        float var = sq * (1.0f / 128.0f) - mu * mu;
        float rs  = rsqrtf(var + 1e-5f);
        if (n < NN) {
            float4 o4;
            o4.x = (h[0] - mu) * rs * ga[0] + ba[0];
            o4.y = (h[1] - mu) * rs * ga[1] + ba[1];
            o4.z = (h[2] - mu) * rs * ga[2] + ba[2];
            o4.w = (h[3] - mu) * rs * ga[3] + ba[3];
            ((float4*)out)[n * 32 + lane] = o4;
        }
    }
}

// ---------------------------------------------------------------------------
extern "C" void kernel_launch(void* const* d_in, const int* in_sizes, int n_in,
                              void* d_out, int out_size) {
    const float* x     = (const float*)d_in[0];
    const float* eh_in = (const float*)d_in[1];
    const float* et_in = (const float*)d_in[2];
    const int*   tidx  = (const int*)  d_in[3];
    const float* tw    = (const float*)d_in[4];
    const float* Wh    = (const float*)d_in[5];
    const float* bh    = (const float*)d_in[6];
    const float* Wt    = (const float*)d_in[7];
    const float* bt    = (const float*)d_in[8];
    const float* W1    = (const float*)d_in[9];
    const float* b1    = (const float*)d_in[10];
    const float* W2    = (const float*)d_in[11];
    const float* b2    = (const float*)d_in[12];
    const float* gamma = (const float*)d_in[13];
    const float* beta  = (const float*)d_in[14];
    float* out = (float*)d_out;

    const int smemA = (D * WS + 64 * D) * (int)sizeof(float);          // 100,352 B
    const int smemB = (2 * D * WS + 2 * 64 * D) * (int)sizeof(float);  // 200,704 B
    cudaFuncSetAttribute(proj_kernel,  cudaFuncAttributeMaxDynamicSharedMemorySize, smemA);
    cudaFuncSetAttribute(fused_kernel, cudaFuncAttributeMaxDynamicSharedMemorySize, smemB);

    const int nblk = (NN + 63) / 64;   // 782
    proj_kernel<<<dim3(nblk, 2), 256, smemA>>>(eh_in, et_in, Wh, bh, Wt, bt);
    fused_kernel<<<nblk, 512, smemB>>>(x, tidx, tw, W1, b1, W2, b2, gamma, beta, out);
}

// round 3
// speedup vs baseline: 1.2848x; 1.2848x over previous
#include <cuda_runtime.h>
#include <cuda_bf16.h>
#include <cstdint>

#define NN   50000
#define DD   128
#define KNB  16
#define NT1  391     // ceil(NN/128)
#define NT2  782     // ceil(NN/64)
#define TILE_B 34816 // 128 rows * 272 B (128 bf16 + 8 pad)
#define UV_B   17408 // 64 rows * 272 B

// ------------------------- global scratch -----------------------------------
__device__ float         g_eh[(size_t)NN * DD];
__device__ float         g_et[(size_t)NN * DD];
__device__ __nv_bfloat16 g_wsp[4][2][DD * DD];   // pre-split weights, row-major

// ------------------------- helpers ------------------------------------------
__device__ __forceinline__ uint32_t smem_u32(const void* p) {
    uint32_t a;
    asm("{ .reg .u64 t; cvta.to.shared.u64 t, %1; cvt.u32.u64 %0, t; }" : "=r"(a) : "l"(p));
    return a;
}
__device__ __forceinline__ uint32_t pack2(__nv_bfloat16 a, __nv_bfloat16 b) {
    __nv_bfloat162 t = __halves2bfloat162(a, b);
    return *(uint32_t*)&t;
}
__device__ __forceinline__ float tanh_fast(float z) {
    z = fminf(15.0f, fmaxf(-15.0f, z));
    float e = __expf(2.0f * z);
    return __fdividef(e - 1.0f, e + 1.0f);
}
__device__ __forceinline__ void cpa16(uint32_t dst, const void* src) {
    asm volatile("cp.async.cg.shared.global [%0], [%1], 16;" :: "r"(dst), "l"(src));
}
#define CP_COMMIT() asm volatile("cp.async.commit_group;")
#define CP_WAIT0()  asm volatile("cp.async.wait_group 0;" ::: "memory")

#define LDSM4(r0, r1, r2, r3, addr) \
    asm volatile("ldmatrix.sync.aligned.m8n8.x4.shared.b16 {%0,%1,%2,%3}, [%4];" \
        : "=r"(r0), "=r"(r1), "=r"(r2), "=r"(r3) : "r"(addr))

#define MMA_BF16(d, a0, a1, a2, a3, b0, b1) \
    asm volatile("mma.sync.aligned.m16n8k16.row.col.f32.bf16.bf16.f32 " \
        "{%0,%1,%2,%3}, {%4,%5,%6,%7}, {%8,%9}, {%0,%1,%2,%3};" \
        : "+f"((d)[0]), "+f"((d)[1]), "+f"((d)[2]), "+f"((d)[3]) \
        : "r"(a0), "r"(a1), "r"(a2), "r"(a3), "r"(b0), "r"(b1))

__device__ __forceinline__ void split4(float4 f, uint2& hv, uint2& lv) {
    __nv_bfloat16 h0 = __float2bfloat16(f.x), h1 = __float2bfloat16(f.y);
    __nv_bfloat16 h2 = __float2bfloat16(f.z), h3 = __float2bfloat16(f.w);
    hv = make_uint2(pack2(h0, h1), pack2(h2, h3));
    lv = make_uint2(
        pack2(__float2bfloat16(f.x - __bfloat162float(h0)), __float2bfloat16(f.y - __bfloat162float(h1))),
        pack2(__float2bfloat16(f.z - __bfloat162float(h2)), __float2bfloat16(f.w - __bfloat162float(h3))));
}

// one 3-pass k-loop over NT ntile-pairs (NT=8 -> 128 cols, NT=4 -> 64 cols)
template <int NT>
__device__ __forceinline__ void gemm_core(uint32_t Ah, uint32_t Al,
                                          uint32_t Bh, uint32_t Bl,
                                          float acc[][4]) {
    #pragma unroll
    for (int pass = 0; pass < 3; pass++) {
        uint32_t Ab = (pass == 2) ? Al : Ah;
        uint32_t Bb = (pass == 1) ? Bl : Bh;
        #pragma unroll
        for (int ks = 0; ks < 8; ks++) {
            uint32_t ka = ks * 32;
            uint32_t a0, a1, a2, a3;
            LDSM4(a0, a1, a2, a3, Ab + ka);
            #pragma unroll
            for (int t = 0; t < NT; t++) {
                uint32_t b0, b1, b2, b3;
                LDSM4(b0, b1, b2, b3, Bb + ka + t * 4352);
                MMA_BF16(acc[2 * t],     a0, a1, a2, a3, b0, b1);
                MMA_BF16(acc[2 * t + 1], a0, a1, a2, a3, b2, b3);
            }
        }
    }
}

// ------------------------- kernel 0: weight split ---------------------------
__global__ void __launch_bounds__(256) k_prep(
    const float* __restrict__ Wh, const float* __restrict__ Wt,
    const float* __restrict__ W1, const float* __restrict__ W2)
{
    int m = blockIdx.x;
    const float* W = (m == 0) ? Wh : (m == 1) ? Wt : (m == 2) ? W1 : W2;
    for (int i = threadIdx.x; i < DD * DD; i += 256) {
        float v = W[i];
        __nv_bfloat16 hi = __float2bfloat16(v);
        g_wsp[m][0][i] = hi;
        g_wsp[m][1][i] = __float2bfloat16(v - __bfloat162float(hi));
    }
}

// ------------------------- kernel 1: projections ----------------------------
#define K1_AH 1024
#define K1_AL (K1_AH + TILE_B)
#define K1_BH (K1_AL + TILE_B)
#define K1_BL (K1_BH + TILE_B)
#define K1_SMEM (K1_BL + TILE_B)   // 140288

__global__ void __launch_bounds__(256) k1_proj(
    const float* __restrict__ eh_in, const float* __restrict__ et_in,
    const float* __restrict__ bh, const float* __restrict__ bt)
{
    extern __shared__ char smc[];
    float* smf = (float*)smc;
    const uint32_t sb = smem_u32(smc);
    const int tid = threadIdx.x, lane = tid & 31, wid = tid >> 5;
    const int n0 = blockIdx.x * 128;

    const float* in; const float* bias; float* outp; int mat;
    if (blockIdx.y == 0) { in = eh_in; bias = bh; outp = g_eh; mat = 0; }
    else                 { in = et_in; bias = bt; outp = g_et; mat = 1; }

    if (tid < 128) smf[tid] = bias[tid];

    // weights hi/lo -> padded smem via cp.async
    {
        const uint4* sh = (const uint4*)g_wsp[mat][0];
        const uint4* sl = (const uint4*)g_wsp[mat][1];
        #pragma unroll
        for (int j = 0; j < 8; j++) {
            int i = tid + j * 256;           // uint4 index: row = i>>4, chunk = i&15
            uint32_t d = sb + (uint32_t)((i >> 4) * 272 + (i & 15) * 16);
            cpa16(d + K1_BH, sh + i);
            cpa16(d + K1_BL, sl + i);
        }
        CP_COMMIT();
    }
    // input tile: load fp32, split to Ah/Al
    {
        const float4* in4 = (const float4*)in;
        #pragma unroll
        for (int j = 0; j < 16; j++) {
            int q = tid + j * 256;           // float4 index: row = q>>5, c4 = q&31
            int row = q >> 5, c4 = q & 31;
            int n = n0 + row;
            float4 f = make_float4(0.f, 0.f, 0.f, 0.f);
            if (n < NN) f = in4[(size_t)n * 32 + c4];
            uint2 hv, lv;
            split4(f, hv, lv);
            uint32_t off = (uint32_t)(row * 272 + c4 * 8);
            *(uint2*)(smc + K1_AH + off) = hv;
            *(uint2*)(smc + K1_AL + off) = lv;
        }
    }
    CP_WAIT0();
    __syncthreads();

    const int m0 = wid * 16;
    float acc[16][4];
    #pragma unroll
    for (int t = 0; t < 16; t++) { acc[t][0] = 0.f; acc[t][1] = 0.f; acc[t][2] = 0.f; acc[t][3] = 0.f; }

    const uint32_t a_off = (uint32_t)((m0 + (lane & 7) + ((lane >> 3) & 1) * 8) * 272 + (lane >> 4) * 16);
    const uint32_t b_off = (uint32_t)(((lane >> 4) * 8 + (lane & 7)) * 272 + ((lane >> 3) & 1) * 16);

    gemm_core<8>(sb + K1_AH + a_off, sb + K1_AL + a_off,
                 sb + K1_BH + b_off, sb + K1_BL + b_off, acc);

    // epilogue: bias + store fp32
    const int r0 = lane >> 2, cs = (lane & 3) * 2;
    #pragma unroll
    for (int t = 0; t < 16; t++) {
        int col = t * 8 + cs;
        float bv0 = smf[col], bv1 = smf[col + 1];
        int na = n0 + m0 + r0, nb2 = na + 8;
        if (na < NN)
            *(float2*)&outp[(size_t)na * DD + col] = make_float2(acc[t][0] + bv0, acc[t][1] + bv1);
        if (nb2 < NN)
            *(float2*)&outp[(size_t)nb2 * DD + col] = make_float2(acc[t][2] + bv0, acc[t][3] + bv1);
    }
}

// ------------------------- kernel 2: attention + GEMMs + LN -----------------
#define K2_W1H 2048
#define K2_W1L (K2_W1H + TILE_B)
#define K2_W2H (K2_W1L + TILE_B)
#define K2_W2L (K2_W2H + TILE_B)
#define K2_UH  (K2_W2L + TILE_B)
#define K2_UL  (K2_UH + UV_B)
#define K2_VH  (K2_UL + UV_B)
#define K2_VL  (K2_VH + UV_B)
#define K2_SMEM (K2_VL + UV_B)     // 210944

__global__ void __launch_bounds__(256) k2_fused(
    const float* __restrict__ x, const int* __restrict__ tidx,
    const float* __restrict__ tw,
    const float* __restrict__ b1, const float* __restrict__ b2,
    const float* __restrict__ gamma, const float* __restrict__ beta,
    float* __restrict__ out)
{
    extern __shared__ char smc[];
    float* smf = (float*)smc;
    const uint32_t sb = smem_u32(smc);
    const int tid = threadIdx.x, lane = tid & 31, wid = tid >> 5;
    const int n0 = blockIdx.x * 64;

    if (tid < 128)      smf[tid] = b1[tid];
    else                smf[tid] = b2[tid - 128];
    if (tid < 128)      smf[256 + tid] = gamma[tid];
    else                smf[256 + tid] = beta[tid - 128];

    // 4 weight tiles via cp.async (overlaps the attention phase)
    {
        const uint4* s0 = (const uint4*)g_wsp[2][0];
        const uint4* s1 = (const uint4*)g_wsp[2][1];
        const uint4* s2 = (const uint4*)g_wsp[3][0];
        const uint4* s3 = (const uint4*)g_wsp[3][1];
        #pragma unroll
        for (int j = 0; j < 8; j++) {
            int i = tid + j * 256;
            uint32_t d = sb + (uint32_t)((i >> 4) * 272 + (i & 15) * 16);
            cpa16(d + K2_W1H, s0 + i);
            cpa16(d + K2_W1L, s1 + i);
            cpa16(d + K2_W2H, s2 + i);
            cpa16(d + K2_W2L, s3 + i);
        }
        CP_COMMIT();
    }

    // ---- attention: warp handles rows wid*8 .. wid*8+7 ----
    for (int rr = 0; rr < 8; rr++) {
        const int rloc = wid * 8 + rr;
        const int n = n0 + rloc;
        uint2 uhv = make_uint2(0u, 0u), ulv = uhv, vhv = uhv, vlv = uhv;
        if (n < NN) {
            float4 eh = ((const float4*)g_eh)[(size_t)n * 32 + lane];
            float4 xr = ((const float4*)x)[(size_t)n * 32 + lane];
            float nb[KNB][4];
            float lg[KNB];
            #pragma unroll
            for (int k = 0; k < KNB; k++) {
                int   id = tidx[(size_t)n * KNB + k];
                float p  = tw[(size_t)n * KNB + k];
                float4 nv = ((const float4*)g_et)[(size_t)id * 32 + lane];
                nb[k][0] = nv.x; nb[k][1] = nv.y; nb[k][2] = nv.z; nb[k][3] = nv.w;
                float q = 2.0f - p;
                float part;
                part  = nv.x * tanh_fast(fmaf(q, eh.x, p * nv.x));
                part += nv.y * tanh_fast(fmaf(q, eh.y, p * nv.y));
                part += nv.z * tanh_fast(fmaf(q, eh.z, p * nv.z));
                part += nv.w * tanh_fast(fmaf(q, eh.w, p * nv.w));
                #pragma unroll
                for (int o = 16; o >= 1; o >>= 1)
                    part += __shfl_xor_sync(0xffffffffu, part, o);
                lg[k] = part;
            }
            float m = lg[0];
            #pragma unroll
            for (int k = 1; k < KNB; k++) m = fmaxf(m, lg[k]);
            float s = 0.f;
            #pragma unroll
            for (int k = 0; k < KNB; k++) { lg[k] = __expf(lg[k] - m); s += lg[k]; }
            float inv = __fdividef(1.0f, s);
            float e0 = 0.f, e1 = 0.f, e2 = 0.f, e3 = 0.f;
            #pragma unroll
            for (int k = 0; k < KNB; k++) {
                float pr = lg[k] * inv;
                e0 = fmaf(pr, nb[k][0], e0);
                e1 = fmaf(pr, nb[k][1], e1);
                e2 = fmaf(pr, nb[k][2], e2);
                e3 = fmaf(pr, nb[k][3], e3);
            }
            float4 u = make_float4(xr.x + e0, xr.y + e1, xr.z + e2, xr.w + e3);
            float4 v = make_float4(xr.x * e0, xr.y * e1, xr.z * e2, xr.w * e3);
            split4(u, uhv, ulv);
            split4(v, vhv, vlv);
        }
        uint32_t off = (uint32_t)(rloc * 272 + lane * 8);
        *(uint2*)(smc + K2_UH + off) = uhv;
        *(uint2*)(smc + K2_UL + off) = ulv;
        *(uint2*)(smc + K2_VH + off) = vhv;
        *(uint2*)(smc + K2_VL + off) = vlv;
    }
    CP_WAIT0();
    __syncthreads();

    // ---- GEMM: warp (mg = wid&3) rows mg*16.., (nh = wid>>2) cols nh*64.. ----
    const int mg = wid & 3, nh = wid >> 2;
    const int m0 = mg * 16, nbase = nh * 64;

    const uint32_t a_off = (uint32_t)((m0 + (lane & 7) + ((lane >> 3) & 1) * 8) * 272 + (lane >> 4) * 16);
    const uint32_t b_off = (uint32_t)((nbase + (lane >> 4) * 8 + (lane & 7)) * 272 + ((lane >> 3) & 1) * 16);

    float acc1[8][4], acc2[8][4];
    #pragma unroll
    for (int t = 0; t < 8; t++) {
        acc1[t][0] = 0.f; acc1[t][1] = 0.f; acc1[t][2] = 0.f; acc1[t][3] = 0.f;
        acc2[t][0] = 0.f; acc2[t][1] = 0.f; acc2[t][2] = 0.f; acc2[t][3] = 0.f;
    }

    gemm_core<4>(sb + K2_UH + a_off, sb + K2_UL + a_off,
                 sb + K2_W1H + b_off, sb + K2_W1L + b_off, acc1);
    gemm_core<4>(sb + K2_VH + a_off, sb + K2_VL + a_off,
                 sb + K2_W2H + b_off, sb + K2_W2L + b_off, acc2);

    __syncthreads();   // all warps done reading U/V tiles -> reuse as hbuf

    // h = leaky(D1+b1) + leaky(D2+b2) -> hbuf [64][132] f32 (reuses UH region)
    float* hb = (float*)(smc + K2_UH);
    {
        const int r0 = lane >> 2, cs = (lane & 3) * 2;
        #pragma unroll
        for (int t = 0; t < 8; t++) {
            int col = nbase + t * 8 + cs;
            float b1v0 = smf[col], b1v1 = smf[col + 1];
            float b2v0 = smf[128 + col], b2v1 = smf[128 + col + 1];
            #pragma unroll
            for (int half = 0; half < 2; half++) {
                int row = m0 + r0 + half * 8;
                float t1a = acc1[t][2 * half + 0] + b1v0;
                float t1b = acc1[t][2 * half + 1] + b1v1;
                t1a = (t1a > 0.f) ? t1a : 0.01f * t1a;
                t1b = (t1b > 0.f) ? t1b : 0.01f * t1b;
                float t2a = acc2[t][2 * half + 0] + b2v0;
                float t2b = acc2[t][2 * half + 1] + b2v1;
                t2a = (t2a > 0.f) ? t2a : 0.01f * t2a;
                t2b = (t2b > 0.f) ? t2b : 0.01f * t2b;
                *(float2*)&hb[row * 132 + col] = make_float2(t1a + t2a, t1b + t2b);
            }
        }
    }
    __syncthreads();

    // layernorm: warp per row, 8 rows each
    float4 gv, bv;
    gv.x = smf[256 + lane * 4 + 0]; gv.y = smf[256 + lane * 4 + 1];
    gv.z = smf[256 + lane * 4 + 2]; gv.w = smf[256 + lane * 4 + 3];
    bv.x = smf[384 + lane * 4 + 0]; bv.y = smf[384 + lane * 4 + 1];
    bv.z = smf[384 + lane * 4 + 2]; bv.w = smf[384 + lane * 4 + 3];
    for (int rr = 0; rr < 8; rr++) {
        int rw = wid * 8 + rr;
        int n = n0 + rw;
        float4 h = *(float4*)&hb[rw * 132 + lane * 4];
        float s  = h.x + h.y + h.z + h.w;
        float sq = h.x * h.x + h.y * h.y + h.z * h.z + h.w * h.w;
        #pragma unroll
        for (int o = 16; o >= 1; o >>= 1) {
            s  += __shfl_xor_sync(0xffffffffu, s,  o);
            sq += __shfl_xor_sync(0xffffffffu, sq, o);
        }
        float mu  = s * (1.0f / 128.0f);
        float var = sq * (1.0f / 128.0f) - mu * mu;
        float rs  = rsqrtf(var + 1e-5f);
        if (n < NN) {
            float4 o4;
            o4.x = (h.x - mu) * rs * gv.x + bv.x;
            o4.y = (h.y - mu) * rs * gv.y + bv.y;
            o4.z = (h.z - mu) * rs * gv.z + bv.z;
            o4.w = (h.w - mu) * rs * gv.w + bv.w;
            ((float4*)out)[(size_t)n * 32 + lane] = o4;
        }
    }
}

// ---------------------------------------------------------------------------
extern "C" void kernel_launch(void* const* d_in, const int* in_sizes, int n_in,
                              void* d_out, int out_size) {
    const float* x     = (const float*)d_in[0];
    const float* eh_in = (const float*)d_in[1];
    const float* et_in = (const float*)d_in[2];
    const int*   tidx  = (const int*)  d_in[3];
    const float* tw    = (const float*)d_in[4];
    const float* Wh    = (const float*)d_in[5];
    const float* bh    = (const float*)d_in[6];
    const float* Wt    = (const float*)d_in[7];
    const float* bt    = (const float*)d_in[8];
    const float* W1    = (const float*)d_in[9];
    const float* b1    = (const float*)d_in[10];
    const float* W2    = (const float*)d_in[11];
    const float* b2    = (const float*)d_in[12];
    const float* gamma = (const float*)d_in[13];
    const float* beta  = (const float*)d_in[14];
    float* out = (float*)d_out;

    cudaFuncSetAttribute(k1_proj,  cudaFuncAttributeMaxDynamicSharedMemorySize, K1_SMEM);
    cudaFuncSetAttribute(k2_fused, cudaFuncAttributeMaxDynamicSharedMemorySize, K2_SMEM);

    k_prep<<<4, 256>>>(Wh, Wt, W1, W2);
    k1_proj<<<dim3(NT1, 2), 256, K1_SMEM>>>(eh_in, et_in, bh, bt);
    k2_fused<<<NT2, 256, K2_SMEM>>>(x, tidx, tw, b1, b2, gamma, beta, out);
}

// round 4
// speedup vs baseline: 1.5614x; 1.2153x over previous
#include <cuda_runtime.h>
#include <cuda_bf16.h>
#include <cstdint>

#define NN   50000
#define DD   128
#define KNB  16
#define NT1  391     // ceil(NN/128)
#define NT2  782     // ceil(NN/64)
#define TILE_B 34816 // 128 rows * 272 B
#define UV_B   17408 // 64 rows * 272 B

// ------------------------- global scratch -----------------------------------
__device__ float         g_eh[(size_t)NN * DD];
__device__ float         g_et[(size_t)NN * DD];
__device__ __nv_bfloat16 g_uh[(size_t)NN * DD];
__device__ __nv_bfloat16 g_ul[(size_t)NN * DD];
__device__ __nv_bfloat16 g_vh[(size_t)NN * DD];
__device__ __nv_bfloat16 g_vl[(size_t)NN * DD];
__device__ __nv_bfloat16 g_wsp[4][2][DD * DD];   // pre-split weights, row-major

// ------------------------- helpers ------------------------------------------
__device__ __forceinline__ uint32_t smem_u32(const void* p) {
    uint32_t a;
    asm("{ .reg .u64 t; cvta.to.shared.u64 t, %1; cvt.u32.u64 %0, t; }" : "=r"(a) : "l"(p));
    return a;
}
__device__ __forceinline__ uint32_t pack2(__nv_bfloat16 a, __nv_bfloat16 b) {
    __nv_bfloat162 t = __halves2bfloat162(a, b);
    return *(uint32_t*)&t;
}
__device__ __forceinline__ float tanh_fast(float z) {
    z = fminf(15.0f, fmaxf(-15.0f, z));
    float e = __expf(2.0f * z);
    return __fdividef(e - 1.0f, e + 1.0f);
}
__device__ __forceinline__ void cpa16(uint32_t dst, const void* src) {
    asm volatile("cp.async.cg.shared.global [%0], [%1], 16;" :: "r"(dst), "l"(src));
}
#define CP_COMMIT() asm volatile("cp.async.commit_group;")
#define CP_WAIT0()  asm volatile("cp.async.wait_group 0;" ::: "memory")

#define LDSM4(r0, r1, r2, r3, addr) \
    asm volatile("ldmatrix.sync.aligned.m8n8.x4.shared.b16 {%0,%1,%2,%3}, [%4];" \
        : "=r"(r0), "=r"(r1), "=r"(r2), "=r"(r3) : "r"(addr))

#define MMA_BF16(d, a0, a1, a2, a3, b0, b1) \
    asm volatile("mma.sync.aligned.m16n8k16.row.col.f32.bf16.bf16.f32 " \
        "{%0,%1,%2,%3}, {%4,%5,%6,%7}, {%8,%9}, {%0,%1,%2,%3};" \
        : "+f"((d)[0]), "+f"((d)[1]), "+f"((d)[2]), "+f"((d)[3]) \
        : "r"(a0), "r"(a1), "r"(a2), "r"(a3), "r"(b0), "r"(b1))

__device__ __forceinline__ void split4(float4 f, uint2& hv, uint2& lv) {
    __nv_bfloat16 h0 = __float2bfloat16(f.x), h1 = __float2bfloat16(f.y);
    __nv_bfloat16 h2 = __float2bfloat16(f.z), h3 = __float2bfloat16(f.w);
    hv = make_uint2(pack2(h0, h1), pack2(h2, h3));
    lv = make_uint2(
        pack2(__float2bfloat16(f.x - __bfloat162float(h0)), __float2bfloat16(f.y - __bfloat162float(h1))),
        pack2(__float2bfloat16(f.z - __bfloat162float(h2)), __float2bfloat16(f.w - __bfloat162float(h3))));
}

// 3-pass bf16-split GEMM k-loop (NT n-tile pairs: NT=8 -> 128 cols, 4 -> 64)
template <int NT>
__device__ __forceinline__ void gemm_core(uint32_t Ah, uint32_t Al,
                                          uint32_t Bh, uint32_t Bl,
                                          float acc[][4]) {
    #pragma unroll
    for (int pass = 0; pass < 3; pass++) {
        uint32_t Ab = (pass == 2) ? Al : Ah;
        uint32_t Bb = (pass == 1) ? Bl : Bh;
        #pragma unroll
        for (int ks = 0; ks < 8; ks++) {
            uint32_t ka = ks * 32;
            uint32_t a0, a1, a2, a3;
            LDSM4(a0, a1, a2, a3, Ab + ka);
            #pragma unroll
            for (int t = 0; t < NT; t++) {
                uint32_t b0, b1, b2, b3;
                LDSM4(b0, b1, b2, b3, Bb + ka + t * 4352);
                MMA_BF16(acc[2 * t],     a0, a1, a2, a3, b0, b1);
                MMA_BF16(acc[2 * t + 1], a0, a1, a2, a3, b2, b3);
            }
        }
    }
}

// ------------------------- kernel 0: weight split (grid 32) -----------------
__global__ void __launch_bounds__(256) k_prep(
    const float* __restrict__ Wh, const float* __restrict__ Wt,
    const float* __restrict__ W1, const float* __restrict__ W2)
{
    int m = blockIdx.x >> 3, part = blockIdx.x & 7;
    const float* W = (m == 0) ? Wh : (m == 1) ? Wt : (m == 2) ? W1 : W2;
    int i = part * 2048 + threadIdx.x;
    #pragma unroll
    for (int j = 0; j < 8; j++, i += 256) {
        float v = W[i];
        __nv_bfloat16 hi = __float2bfloat16(v);
        g_wsp[m][0][i] = hi;
        g_wsp[m][1][i] = __float2bfloat16(v - __bfloat162float(hi));
    }
}

// ------------------------- kernel 1: projections ----------------------------
#define K1_AH 1024
#define K1_AL (K1_AH + TILE_B)
#define K1_BH (K1_AL + TILE_B)
#define K1_BL (K1_BH + TILE_B)
#define K1_SMEM (K1_BL + TILE_B)   // 140288

__global__ void __launch_bounds__(256) k1_proj(
    const float* __restrict__ eh_in, const float* __restrict__ et_in,
    const float* __restrict__ bh, const float* __restrict__ bt)
{
    extern __shared__ char smc[];
    float* smf = (float*)smc;
    const uint32_t sb = smem_u32(smc);
    const int tid = threadIdx.x, lane = tid & 31, wid = tid >> 5;
    const int n0 = blockIdx.x * 128;

    const float* in; const float* bias; float* outp; int mat;
    if (blockIdx.y == 0) { in = eh_in; bias = bh; outp = g_eh; mat = 0; }
    else                 { in = et_in; bias = bt; outp = g_et; mat = 1; }

    if (tid < 128) smf[tid] = bias[tid];

    {
        const uint4* sh = (const uint4*)g_wsp[mat][0];
        const uint4* sl = (const uint4*)g_wsp[mat][1];
        #pragma unroll
        for (int j = 0; j < 8; j++) {
            int i = tid + j * 256;
            uint32_t d = sb + (uint32_t)((i >> 4) * 272 + (i & 15) * 16);
            cpa16(d + K1_BH, sh + i);
            cpa16(d + K1_BL, sl + i);
        }
        CP_COMMIT();
    }
    {
        const float4* in4 = (const float4*)in;
        #pragma unroll
        for (int j = 0; j < 16; j++) {
            int q = tid + j * 256;
            int row = q >> 5, c4 = q & 31;
            int n = n0 + row;
            float4 f = make_float4(0.f, 0.f, 0.f, 0.f);
            if (n < NN) f = in4[(size_t)n * 32 + c4];
            uint2 hv, lv;
            split4(f, hv, lv);
            uint32_t off = (uint32_t)(row * 272 + c4 * 8);
            *(uint2*)(smc + K1_AH + off) = hv;
            *(uint2*)(smc + K1_AL + off) = lv;
        }
    }
    CP_WAIT0();
    __syncthreads();

    const int m0 = wid * 16;
    float acc[16][4];
    #pragma unroll
    for (int t = 0; t < 16; t++) { acc[t][0] = 0.f; acc[t][1] = 0.f; acc[t][2] = 0.f; acc[t][3] = 0.f; }

    const uint32_t a_off = (uint32_t)((m0 + (lane & 7) + ((lane >> 3) & 1) * 8) * 272 + (lane >> 4) * 16);
    const uint32_t b_off = (uint32_t)(((lane >> 4) * 8 + (lane & 7)) * 272 + ((lane >> 3) & 1) * 16);

    gemm_core<8>(sb + K1_AH + a_off, sb + K1_AL + a_off,
                 sb + K1_BH + b_off, sb + K1_BL + b_off, acc);

    const int r0 = lane >> 2, cs = (lane & 3) * 2;
    #pragma unroll
    for (int t = 0; t < 16; t++) {
        int col = t * 8 + cs;
        float bv0 = smf[col], bv1 = smf[col + 1];
        int na = n0 + m0 + r0, nb2 = na + 8;
        if (na < NN)
            *(float2*)&outp[(size_t)na * DD + col] = make_float2(acc[t][0] + bv0, acc[t][1] + bv1);
        if (nb2 < NN)
            *(float2*)&outp[(size_t)nb2 * DD + col] = make_float2(acc[t][2] + bv0, acc[t][3] + bv1);
    }
}

// ------------------------- kernel 2a: attention only (no smem) --------------
__global__ void __launch_bounds__(256, 2) k2_attn(
    const float* __restrict__ x, const int* __restrict__ tidx,
    const float* __restrict__ tw)
{
    const int tid = threadIdx.x, lane = tid & 31, wid = tid >> 5;
    const int n0 = blockIdx.x * 32;

    #pragma unroll 1
    for (int rr = 0; rr < 4; rr++) {
        const int n = n0 + wid * 4 + rr;
        if (n >= NN) continue;
        float4 eh = ((const float4*)g_eh)[(size_t)n * 32 + lane];
        float4 xr = ((const float4*)x)[(size_t)n * 32 + lane];
        float nb[KNB][4];
        float lg[KNB];
        #pragma unroll
        for (int k = 0; k < KNB; k++) {
            int   id = tidx[(size_t)n * KNB + k];
            float p  = tw[(size_t)n * KNB + k];
            float4 nv = ((const float4*)g_et)[(size_t)id * 32 + lane];
            nb[k][0] = nv.x; nb[k][1] = nv.y; nb[k][2] = nv.z; nb[k][3] = nv.w;
            float q = 2.0f - p;
            float part;
            part  = nv.x * tanh_fast(fmaf(q, eh.x, p * nv.x));
            part += nv.y * tanh_fast(fmaf(q, eh.y, p * nv.y));
            part += nv.z * tanh_fast(fmaf(q, eh.z, p * nv.z));
            part += nv.w * tanh_fast(fmaf(q, eh.w, p * nv.w));
            #pragma unroll
            for (int o = 16; o >= 1; o >>= 1)
                part += __shfl_xor_sync(0xffffffffu, part, o);
            lg[k] = part;
        }
        float m = lg[0];
        #pragma unroll
        for (int k = 1; k < KNB; k++) m = fmaxf(m, lg[k]);
        float s = 0.f;
        #pragma unroll
        for (int k = 0; k < KNB; k++) { lg[k] = __expf(lg[k] - m); s += lg[k]; }
        float inv = __fdividef(1.0f, s);
        float e0 = 0.f, e1 = 0.f, e2 = 0.f, e3 = 0.f;
        #pragma unroll
        for (int k = 0; k < KNB; k++) {
            float pr = lg[k] * inv;
            e0 = fmaf(pr, nb[k][0], e0);
            e1 = fmaf(pr, nb[k][1], e1);
            e2 = fmaf(pr, nb[k][2], e2);
            e3 = fmaf(pr, nb[k][3], e3);
        }
        float4 u = make_float4(xr.x + e0, xr.y + e1, xr.z + e2, xr.w + e3);
        float4 v = make_float4(xr.x * e0, xr.y * e1, xr.z * e2, xr.w * e3);
        uint2 uhv, ulv, vhv, vlv;
        split4(u, uhv, ulv);
        split4(v, vhv, vlv);
        ((uint2*)(g_uh + (size_t)n * DD))[lane] = uhv;
        ((uint2*)(g_ul + (size_t)n * DD))[lane] = ulv;
        ((uint2*)(g_vh + (size_t)n * DD))[lane] = vhv;
        ((uint2*)(g_vl + (size_t)n * DD))[lane] = vlv;
    }
}

// ------------------------- kernel 3: GEMMs + LN -----------------------------
#define K3_W1H 2048
#define K3_W1L (K3_W1H + TILE_B)
#define K3_W2H (K3_W1L + TILE_B)
#define K3_W2L (K3_W2H + TILE_B)
#define K3_UH  (K3_W2L + TILE_B)
#define K3_UL  (K3_UH + UV_B)
#define K3_VH  (K3_UL + UV_B)
#define K3_VL  (K3_VH + UV_B)
#define K3_SMEM (K3_VL + UV_B)     // 210944

__global__ void __launch_bounds__(256) k3_out(
    const float* __restrict__ b1, const float* __restrict__ b2,
    const float* __restrict__ gamma, const float* __restrict__ beta,
    float* __restrict__ out)
{
    extern __shared__ char smc[];
    float* smf = (float*)smc;
    const uint32_t sb = smem_u32(smc);
    const int tid = threadIdx.x, lane = tid & 31, wid = tid >> 5;
    const int n0 = blockIdx.x * 64;

    if (tid < 128)      smf[tid] = b1[tid];
    else                smf[tid] = b2[tid - 128];
    if (tid < 128)      smf[256 + tid] = gamma[tid];
    else                smf[256 + tid] = beta[tid - 128];

    // weights (L2-resident after first wave)
    {
        const uint4* s0 = (const uint4*)g_wsp[2][0];
        const uint4* s1 = (const uint4*)g_wsp[2][1];
        const uint4* s2 = (const uint4*)g_wsp[3][0];
        const uint4* s3 = (const uint4*)g_wsp[3][1];
        #pragma unroll
        for (int j = 0; j < 8; j++) {
            int i = tid + j * 256;
            uint32_t d = sb + (uint32_t)((i >> 4) * 272 + (i & 15) * 16);
            cpa16(d + K3_W1H, s0 + i);
            cpa16(d + K3_W1L, s1 + i);
            cpa16(d + K3_W2H, s2 + i);
            cpa16(d + K3_W2L, s3 + i);
        }
    }
    // U/V tiles: 64 rows x 256 B each (bf16), 1024 16B-chunks per tile
    {
        #pragma unroll
        for (int j = 0; j < 4; j++) {
            int i = tid + j * 256;           // chunk: row = i>>4, c = i&15
            int row = i >> 4, c = i & 15;
            int n = n0 + row;
            if (n < NN) {
                uint32_t d = sb + (uint32_t)(row * 272 + c * 16);
                const char* srcoff = (const char*)nullptr + ((size_t)n * 256 + c * 16);
                cpa16(d + K3_UH, (const char*)g_uh + ((size_t)n * 256 + (size_t)c * 16));
                cpa16(d + K3_UL, (const char*)g_ul + ((size_t)n * 256 + (size_t)c * 16));
                cpa16(d + K3_VH, (const char*)g_vh + ((size_t)n * 256 + (size_t)c * 16));
                cpa16(d + K3_VL, (const char*)g_vl + ((size_t)n * 256 + (size_t)c * 16));
                (void)srcoff;
            }
        }
        CP_COMMIT();
    }
    CP_WAIT0();
    __syncthreads();

    const int mg = wid & 3, nh = wid >> 2;
    const int m0 = mg * 16, nbase = nh * 64;

    const uint32_t a_off = (uint32_t)((m0 + (lane & 7) + ((lane >> 3) & 1) * 8) * 272 + (lane >> 4) * 16);
    const uint32_t b_off = (uint32_t)((nbase + (lane >> 4) * 8 + (lane & 7)) * 272 + ((lane >> 3) & 1) * 16);

    float acc1[8][4], acc2[8][4];
    #pragma unroll
    for (int t = 0; t < 8; t++) {
        acc1[t][0] = 0.f; acc1[t][1] = 0.f; acc1[t][2] = 0.f; acc1[t][3] = 0.f;
        acc2[t][0] = 0.f; acc2[t][1] = 0.f; acc2[t][2] = 0.f; acc2[t][3] = 0.f;
    }

    gemm_core<4>(sb + K3_UH + a_off, sb + K3_UL + a_off,
                 sb + K3_W1H + b_off, sb + K3_W1L + b_off, acc1);
    gemm_core<4>(sb + K3_VH + a_off, sb + K3_VL + a_off,
                 sb + K3_W2H + b_off, sb + K3_W2L + b_off, acc2);

    __syncthreads();   // done reading U/V tiles -> reuse as hbuf

    float* hb = (float*)(smc + K3_UH);
    {
        const int r0 = lane >> 2, cs = (lane & 3) * 2;
        #pragma unroll
        for (int t = 0; t < 8; t++) {
            int col = nbase + t * 8 + cs;
            float b1v0 = smf[col], b1v1 = smf[col + 1];
            float b2v0 = smf[128 + col], b2v1 = smf[128 + col + 1];
            #pragma unroll
            for (int half = 0; half < 2; half++) {
                int row = m0 + r0 + half * 8;
                float t1a = acc1[t][2 * half + 0] + b1v0;
                float t1b = acc1[t][2 * half + 1] + b1v1;
                t1a = (t1a > 0.f) ? t1a : 0.01f * t1a;
                t1b = (t1b > 0.f) ? t1b : 0.01f * t1b;
                float t2a = acc2[t][2 * half + 0] + b2v0;
                float t2b = acc2[t][2 * half + 1] + b2v1;
                t2a = (t2a > 0.f) ? t2a : 0.01f * t2a;
                t2b = (t2b > 0.f) ? t2b : 0.01f * t2b;
                *(float2*)&hb[row * 132 + col] = make_float2(t1a + t2a, t1b + t2b);
            }
        }
    }
    __syncthreads();

    float4 gv, bv;
    gv.x = smf[256 + lane * 4 + 0]; gv.y = smf[256 + lane * 4 + 1];
    gv.z = smf[256 + lane * 4 + 2]; gv.w = smf[256 + lane * 4 + 3];
    bv.x = smf[384 + lane * 4 + 0]; bv.y = smf[384 + lane * 4 + 1];
    bv.z = smf[384 + lane * 4 + 2]; bv.w = smf[384 + lane * 4 + 3];
    #pragma unroll 1
    for (int rr = 0; rr < 8; rr++) {
        int rw = wid * 8 + rr;
        int n = n0 + rw;
        float4 h = *(float4*)&hb[rw * 132 + lane * 4];
        float s  = h.x + h.y + h.z + h.w;
        float sq = h.x * h.x + h.y * h.y + h.z * h.z + h.w * h.w;
        #pragma unroll
        for (int o = 16; o >= 1; o >>= 1) {
            s  += __shfl_xor_sync(0xffffffffu, s,  o);
            sq += __shfl_xor_sync(0xffffffffu, sq, o);
        }
        float mu  = s * (1.0f / 128.0f);
        float var = sq * (1.0f / 128.0f) - mu * mu;
        float rs  = rsqrtf(var + 1e-5f);
        if (n < NN) {
            float4 o4;
            o4.x = (h.x - mu) * rs * gv.x + bv.x;
            o4.y = (h.y - mu) * rs * gv.y + bv.y;
            o4.z = (h.z - mu) * rs * gv.z + bv.z;
            o4.w = (h.w - mu) * rs * gv.w + bv.w;
            ((float4*)out)[(size_t)n * 32 + lane] = o4;
        }
    }
}

// ---------------------------------------------------------------------------
extern "C" void kernel_launch(void* const* d_in, const int* in_sizes, int n_in,
                              void* d_out, int out_size) {
    const float* x     = (const float*)d_in[0];
    const float* eh_in = (const float*)d_in[1];
    const float* et_in = (const float*)d_in[2];
    const int*   tidx  = (const int*)  d_in[3];
    const float* tw    = (const float*)d_in[4];
    const float* Wh    = (const float*)d_in[5];
    const float* bh    = (const float*)d_in[6];
    const float* Wt    = (const float*)d_in[7];
    const float* bt    = (const float*)d_in[8];
    const float* W1    = (const float*)d_in[9];
    const float* b1    = (const float*)d_in[10];
    const float* W2    = (const float*)d_in[11];
    const float* b2    = (const float*)d_in[12];
    const float* gamma = (const float*)d_in[13];
    const float* beta  = (const float*)d_in[14];
    float* out = (float*)d_out;

    cudaFuncSetAttribute(k1_proj, cudaFuncAttributeMaxDynamicSharedMemorySize, K1_SMEM);
    cudaFuncSetAttribute(k3_out,  cudaFuncAttributeMaxDynamicSharedMemorySize, K3_SMEM);

    k_prep<<<32, 256>>>(Wh, Wt, W1, W2);
    k1_proj<<<dim3(NT1, 2), 256, K1_SMEM>>>(eh_in, et_in, bh, bt);
    k2_attn<<<(NN + 31) / 32, 256>>>(x, tidx, tw);
    k3_out<<<NT2, 256, K3_SMEM>>>(b1, b2, gamma, beta, out);
}

// round 5
// speedup vs baseline: 1.8911x; 1.2112x over previous
#include <cuda_runtime.h>
#include <cuda_bf16.h>
#include <cstdint>

#define NN     50000
#define DD     128
#define KNB    16
#define NTILES 1563    // ceil(NN/32)
#define NSM    148

// ------------------------- global scratch -----------------------------------
__device__ float         g_eh[(size_t)NN * DD];
__device__ float         g_et[(size_t)NN * DD];
__device__ __nv_bfloat16 g_uh[(size_t)NN * DD];
__device__ __nv_bfloat16 g_ul[(size_t)NN * DD];
__device__ __nv_bfloat16 g_vh[(size_t)NN * DD];
__device__ __nv_bfloat16 g_vl[(size_t)NN * DD];

// ------------------------- helpers ------------------------------------------
__device__ __forceinline__ uint32_t smem_u32(const void* p) {
    uint32_t a;
    asm("{ .reg .u64 t; cvta.to.shared.u64 t, %1; cvt.u32.u64 %0, t; }" : "=r"(a) : "l"(p));
    return a;
}
__device__ __forceinline__ uint32_t pack2(__nv_bfloat16 a, __nv_bfloat16 b) {
    __nv_bfloat162 t = __halves2bfloat162(a, b);
    return *(uint32_t*)&t;
}
__device__ __forceinline__ float tanh_fast(float z) {
    z = fminf(15.0f, fmaxf(-15.0f, z));
    float e = __expf(2.0f * z);
    return __fdividef(e - 1.0f, e + 1.0f);
}
__device__ __forceinline__ void cpa16(uint32_t dst, const void* src) {
    asm volatile("cp.async.cg.shared.global [%0], [%1], 16;" :: "r"(dst), "l"(src));
}
#define CP_COMMIT() asm volatile("cp.async.commit_group;")
#define CP_WAIT1()  asm volatile("cp.async.wait_group 1;" ::: "memory")

#define LDSM4(r0, r1, r2, r3, addr) \
    asm volatile("ldmatrix.sync.aligned.m8n8.x4.shared.b16 {%0,%1,%2,%3}, [%4];" \
        : "=r"(r0), "=r"(r1), "=r"(r2), "=r"(r3) : "r"(addr))

#define MMA_BF16(d, a0, a1, a2, a3, b0, b1) \
    asm volatile("mma.sync.aligned.m16n8k16.row.col.f32.bf16.bf16.f32 " \
        "{%0,%1,%2,%3}, {%4,%5,%6,%7}, {%8,%9}, {%0,%1,%2,%3};" \
        : "+f"((d)[0]), "+f"((d)[1]), "+f"((d)[2]), "+f"((d)[3]) \
        : "r"(a0), "r"(a1), "r"(a2), "r"(a3), "r"(b0), "r"(b1))

__device__ __forceinline__ void split4(float4 f, uint2& hv, uint2& lv) {
    __nv_bfloat16 h0 = __float2bfloat16(f.x), h1 = __float2bfloat16(f.y);
    __nv_bfloat16 h2 = __float2bfloat16(f.z), h3 = __float2bfloat16(f.w);
    hv = make_uint2(pack2(h0, h1), pack2(h2, h3));
    lv = make_uint2(
        pack2(__float2bfloat16(f.x - __bfloat162float(h0)), __float2bfloat16(f.y - __bfloat162float(h1))),
        pack2(__float2bfloat16(f.z - __bfloat162float(h2)), __float2bfloat16(f.w - __bfloat162float(h3))));
}

// split a 128x128 fp32 weight matrix into hi/lo bf16 padded smem tiles
__device__ __forceinline__ void w_split_to_smem(const float* W, char* smc,
                                                int hbase, int tid) {
    const float4* W4 = (const float4*)W;
    #pragma unroll
    for (int j = 0; j < 16; j++) {
        int i = tid + j * 256;               // float4 index 0..4095
        int row = i >> 5, c4 = i & 31;
        uint2 hv, lv;
        split4(W4[i], hv, lv);
        uint32_t off = (uint32_t)(row * 272 + c4 * 8);
        *(uint2*)(smc + hbase + off)         = hv;
        *(uint2*)(smc + hbase + 34816 + off) = lv;
    }
}

// ------------------------- kernel 1: persistent projections -----------------
// smem: [0,1024) biases; Wh hi/lo @1024/35840; Wt hi/lo @70656/105472;
//       A tiles: eh hi/lo @140288/148992, et hi/lo @157696/166400
#define K1_WHH 1024
#define K1_WTH 70656
#define K1_AEH 140288
#define K1_AET 157696
#define K1_SMEM 175104

__global__ void __launch_bounds__(256) k1_proj(
    const float* __restrict__ eh_in, const float* __restrict__ et_in,
    const float* __restrict__ Wh, const float* __restrict__ bh,
    const float* __restrict__ Wt, const float* __restrict__ bt)
{
    extern __shared__ char smc[];
    float* smf = (float*)smc;
    const uint32_t sb = smem_u32(smc);
    const int tid = threadIdx.x, lane = tid & 31, wid = tid >> 5;

    // prefetch first input tile into registers (overlaps weight conversion)
    float4 f[8];
    {
        int n0 = blockIdx.x * 32;
        #pragma unroll
        for (int j = 0; j < 8; j++) {
            int i = tid + j * 256;
            int inp = i >> 10, row = (i >> 5) & 31, c4 = i & 31;
            int n = n0 + row;
            f[j] = (n < NN) ? ((const float4*)(inp ? et_in : eh_in))[(size_t)n * 32 + c4]
                            : make_float4(0.f, 0.f, 0.f, 0.f);
        }
    }

    if (tid < 128) smf[tid] = bh[tid];
    else           smf[tid] = bt[tid - 128];
    w_split_to_smem(Wh, smc, K1_WHH, tid);
    w_split_to_smem(Wt, smc, K1_WTH, tid);
    __syncthreads();

    const int mat   = wid >> 2;
    const int nbase = (wid & 3) * 32;
    const uint32_t Ah = sb + (mat ? K1_AET : K1_AEH);
    const uint32_t Al = Ah + 8704;
    const uint32_t Bh = sb + (mat ? K1_WTH : K1_WHH);
    const uint32_t Bl = Bh + 34816;
    const uint32_t a_off = (uint32_t)(((lane & 7) + ((lane >> 3) & 1) * 8) * 272 + (lane >> 4) * 16);
    const uint32_t b_off = (uint32_t)((nbase + (lane >> 4) * 8 + (lane & 7)) * 272 + ((lane >> 3) & 1) * 16);
    float* outp = mat ? g_et : g_eh;
    const float* bias = smf + mat * 128;
    const int r0 = lane >> 2, cs = (lane & 3) * 2;

    for (int tile = blockIdx.x; tile < NTILES; tile += NSM) {
        // convert current tile regs -> A smem tiles
        #pragma unroll
        for (int j = 0; j < 8; j++) {
            int i = tid + j * 256;
            int inp = i >> 10, row = (i >> 5) & 31, c4 = i & 31;
            uint2 hv, lv;
            split4(f[j], hv, lv);
            uint32_t base = inp ? K1_AET : K1_AEH;
            uint32_t off = (uint32_t)(row * 272 + c4 * 8);
            *(uint2*)(smc + base + off)        = hv;
            *(uint2*)(smc + base + 8704 + off) = lv;
        }
        // prefetch next tile
        {
            int nt = tile + NSM;
            if (nt < NTILES) {
                int n0 = nt * 32;
                #pragma unroll
                for (int j = 0; j < 8; j++) {
                    int i = tid + j * 256;
                    int inp = i >> 10, row = (i >> 5) & 31, c4 = i & 31;
                    int n = n0 + row;
                    f[j] = (n < NN) ? ((const float4*)(inp ? et_in : eh_in))[(size_t)n * 32 + c4]
                                    : make_float4(0.f, 0.f, 0.f, 0.f);
                }
            }
        }
        __syncthreads();

        float acc[2][4][4];
        #pragma unroll
        for (int mt = 0; mt < 2; mt++)
            #pragma unroll
            for (int t = 0; t < 4; t++) {
                acc[mt][t][0] = 0.f; acc[mt][t][1] = 0.f; acc[mt][t][2] = 0.f; acc[mt][t][3] = 0.f;
            }

        #pragma unroll
        for (int pass = 0; pass < 3; pass++) {
            uint32_t A = ((pass == 2) ? Al : Ah) + a_off;
            uint32_t B = ((pass == 1) ? Bl : Bh) + b_off;
            #pragma unroll
            for (int ks = 0; ks < 8; ks++) {
                uint32_t ka = ks * 32;
                uint32_t a0, a1, a2, a3, a4, a5, a6, a7;
                LDSM4(a0, a1, a2, a3, A + ka);
                LDSM4(a4, a5, a6, a7, A + ka + 16 * 272);
                #pragma unroll
                for (int bt = 0; bt < 2; bt++) {
                    uint32_t b0, b1, b2, b3;
                    LDSM4(b0, b1, b2, b3, B + ka + bt * 4352);
                    MMA_BF16(acc[0][2 * bt],     a0, a1, a2, a3, b0, b1);
                    MMA_BF16(acc[0][2 * bt + 1], a0, a1, a2, a3, b2, b3);
                    MMA_BF16(acc[1][2 * bt],     a4, a5, a6, a7, b0, b1);
                    MMA_BF16(acc[1][2 * bt + 1], a4, a5, a6, a7, b2, b3);
                }
            }
        }

        // epilogue: bias + fp32 store
        int n0 = tile * 32;
        #pragma unroll
        for (int mt = 0; mt < 2; mt++) {
            #pragma unroll
            for (int t = 0; t < 4; t++) {
                int col = nbase + t * 8 + cs;
                float bv0 = bias[col], bv1 = bias[col + 1];
                int na = n0 + mt * 16 + r0, nb2 = na + 8;
                if (na < NN)
                    *(float2*)&outp[(size_t)na * DD + col] =
                        make_float2(acc[mt][t][0] + bv0, acc[mt][t][1] + bv1);
                if (nb2 < NN)
                    *(float2*)&outp[(size_t)nb2 * DD + col] =
                        make_float2(acc[mt][t][2] + bv0, acc[mt][t][3] + bv1);
            }
        }
        __syncthreads();   // all gemm reads done before next conv overwrite
    }
}

// ------------------------- kernel 2: attention (unchanged math) -------------
__global__ void __launch_bounds__(256, 2) k2_attn(
    const float* __restrict__ x, const int* __restrict__ tidx,
    const float* __restrict__ tw)
{
    const int tid = threadIdx.x, lane = tid & 31, wid = tid >> 5;
    const int n0 = blockIdx.x * 32;

    #pragma unroll 1
    for (int rr = 0; rr < 4; rr++) {
        const int n = n0 + wid * 4 + rr;
        if (n >= NN) continue;
        float4 eh = ((const float4*)g_eh)[(size_t)n * 32 + lane];
        float4 xr = ((const float4*)x)[(size_t)n * 32 + lane];
        float nb[KNB][4];
        float lg[KNB];
        #pragma unroll
        for (int k = 0; k < KNB; k++) {
            int   id = tidx[(size_t)n * KNB + k];
            float p  = tw[(size_t)n * KNB + k];
            float4 nv = ((const float4*)g_et)[(size_t)id * 32 + lane];
            nb[k][0] = nv.x; nb[k][1] = nv.y; nb[k][2] = nv.z; nb[k][3] = nv.w;
            float q = 2.0f - p;
            float part;
            part  = nv.x * tanh_fast(fmaf(q, eh.x, p * nv.x));
            part += nv.y * tanh_fast(fmaf(q, eh.y, p * nv.y));
            part += nv.z * tanh_fast(fmaf(q, eh.z, p * nv.z));
            part += nv.w * tanh_fast(fmaf(q, eh.w, p * nv.w));
            #pragma unroll
            for (int o = 16; o >= 1; o >>= 1)
                part += __shfl_xor_sync(0xffffffffu, part, o);
            lg[k] = part;
        }
        float m = lg[0];
        #pragma unroll
        for (int k = 1; k < KNB; k++) m = fmaxf(m, lg[k]);
        float s = 0.f;
        #pragma unroll
        for (int k = 0; k < KNB; k++) { lg[k] = __expf(lg[k] - m); s += lg[k]; }
        float inv = __fdividef(1.0f, s);
        float e0 = 0.f, e1 = 0.f, e2 = 0.f, e3 = 0.f;
        #pragma unroll
        for (int k = 0; k < KNB; k++) {
            float pr = lg[k] * inv;
            e0 = fmaf(pr, nb[k][0], e0);
            e1 = fmaf(pr, nb[k][1], e1);
            e2 = fmaf(pr, nb[k][2], e2);
            e3 = fmaf(pr, nb[k][3], e3);
        }
        float4 u = make_float4(xr.x + e0, xr.y + e1, xr.z + e2, xr.w + e3);
        float4 v = make_float4(xr.x * e0, xr.y * e1, xr.z * e2, xr.w * e3);
        uint2 uhv, ulv, vhv, vlv;
        split4(u, uhv, ulv);
        split4(v, vhv, vlv);
        ((uint2*)(g_uh + (size_t)n * DD))[lane] = uhv;
        ((uint2*)(g_ul + (size_t)n * DD))[lane] = ulv;
        ((uint2*)(g_vh + (size_t)n * DD))[lane] = vhv;
        ((uint2*)(g_vl + (size_t)n * DD))[lane] = vlv;
    }
}

// ------------------------- kernel 3: persistent GEMMs + LN ------------------
// smem: [0,2048) consts; W1 hi/lo @2048/36864; W2 hi/lo @71680/106496;
//       stage0 @141312, stage1 @176128 (each: uh,ul,vh,vl x 8704)
#define K3_W1H 2048
#define K3_W2H 71680
#define K3_S0  141312
#define K3_S1  176128
#define K3_SMEM 210944

__device__ __forceinline__ void k3_prefetch(int tile, uint32_t stage, int tid) {
    int n0 = tile * 32;
    #pragma unroll
    for (int j = 0; j < 8; j++) {
        int i = tid + j * 256;
        int arr = i >> 9, row = (i >> 4) & 31, c = i & 15;
        int n = n0 + row;
        if (n < NN) {
            const __nv_bfloat16* src = (arr == 0) ? g_uh : (arr == 1) ? g_ul
                                      : (arr == 2) ? g_vh : g_vl;
            cpa16(stage + (uint32_t)(arr * 8704 + row * 272 + c * 16),
                  (const char*)src + ((size_t)n * 256 + (size_t)c * 16));
        }
    }
    CP_COMMIT();
}

__global__ void __launch_bounds__(256) k3_out(
    const float* __restrict__ W1, const float* __restrict__ b1,
    const float* __restrict__ W2, const float* __restrict__ b2,
    const float* __restrict__ gamma, const float* __restrict__ beta,
    float* __restrict__ out)
{
    extern __shared__ char smc[];
    float* smf = (float*)smc;
    const uint32_t sb = smem_u32(smc);
    const int tid = threadIdx.x, lane = tid & 31, wid = tid >> 5;

    // first stage prefetch before weight conversion (overlap)
    k3_prefetch(blockIdx.x, sb + K3_S0, tid);

    if (tid < 128) { smf[tid] = b1[tid];       smf[256 + tid] = gamma[tid]; }
    else           { smf[tid] = b2[tid - 128]; smf[256 + tid] = beta[tid - 128]; }
    w_split_to_smem(W1, smc, K3_W1H, tid);
    w_split_to_smem(W2, smc, K3_W2H, tid);

    const int mrow0 = (wid & 1) * 16;
    const int ncol0 = (wid >> 1) * 32;
    const uint32_t a_off = (uint32_t)((mrow0 + (lane & 7) + ((lane >> 3) & 1) * 8) * 272 + (lane >> 4) * 16);
    const uint32_t b_off = (uint32_t)((ncol0 + (lane >> 4) * 8 + (lane & 7)) * 272 + ((lane >> 3) & 1) * 16);
    const int r0 = lane >> 2, cs = (lane & 3) * 2;

    float4 gv, bvv;
    gv.x  = smf[256 + lane * 4 + 0]; gv.y  = smf[256 + lane * 4 + 1];
    gv.z  = smf[256 + lane * 4 + 2]; gv.w  = smf[256 + lane * 4 + 3];
    bvv.x = smf[384 + lane * 4 + 0]; bvv.y = smf[384 + lane * 4 + 1];
    bvv.z = smf[384 + lane * 4 + 2]; bvv.w = smf[384 + lane * 4 + 3];

    int cur = 0;
    for (int tile = blockIdx.x; tile < NTILES; tile += NSM) {
        int nt = tile + NSM;
        if (nt < NTILES) k3_prefetch(nt, sb + (cur ? K3_S0 : K3_S1), tid);
        else             CP_COMMIT();
        CP_WAIT1();
        __syncthreads();

        const uint32_t S = sb + (cur ? K3_S1 : K3_S0);
        float accU[4][4], accV[4][4];
        #pragma unroll
        for (int t = 0; t < 4; t++) {
            accU[t][0] = 0.f; accU[t][1] = 0.f; accU[t][2] = 0.f; accU[t][3] = 0.f;
            accV[t][0] = 0.f; accV[t][1] = 0.f; accV[t][2] = 0.f; accV[t][3] = 0.f;
        }

        #pragma unroll
        for (int pass = 0; pass < 3; pass++) {
            uint32_t Au = S + ((pass == 2) ? 8704u : 0u) + a_off;
            uint32_t Av = Au + 17408u;
            uint32_t B1 = sb + ((pass == 1) ? (K3_W1H + 34816) : K3_W1H) + b_off;
            uint32_t B2 = sb + ((pass == 1) ? (K3_W2H + 34816) : K3_W2H) + b_off;
            #pragma unroll
            for (int ks = 0; ks < 8; ks++) {
                uint32_t ka = ks * 32;
                uint32_t u0, u1, u2, u3, v0, v1, v2, v3;
                LDSM4(u0, u1, u2, u3, Au + ka);
                LDSM4(v0, v1, v2, v3, Av + ka);
                #pragma unroll
                for (int bt = 0; bt < 2; bt++) {
                    uint32_t c0, c1, c2, c3;
                    LDSM4(c0, c1, c2, c3, B1 + ka + bt * 4352);
                    MMA_BF16(accU[2 * bt],     u0, u1, u2, u3, c0, c1);
                    MMA_BF16(accU[2 * bt + 1], u0, u1, u2, u3, c2, c3);
                    uint32_t d0, d1, d2, d3;
                    LDSM4(d0, d1, d2, d3, B2 + ka + bt * 4352);
                    MMA_BF16(accV[2 * bt],     v0, v1, v2, v3, d0, d1);
                    MMA_BF16(accV[2 * bt + 1], v0, v1, v2, v3, d2, d3);
                }
            }
        }
        __syncthreads();   // gemm reads done -> reuse stage as hbuf

        float* hb = (float*)(smc + (cur ? K3_S1 : K3_S0));
        #pragma unroll
        for (int t = 0; t < 4; t++) {
            int col = ncol0 + t * 8 + cs;
            float b1v0 = smf[col], b1v1 = smf[col + 1];
            float b2v0 = smf[128 + col], b2v1 = smf[128 + col + 1];
            #pragma unroll
            for (int half = 0; half < 2; half++) {
                int row = mrow0 + r0 + half * 8;
                float t1a = accU[t][2 * half + 0] + b1v0;
                float t1b = accU[t][2 * half + 1] + b1v1;
                t1a = (t1a > 0.f) ? t1a : 0.01f * t1a;
                t1b = (t1b > 0.f) ? t1b : 0.01f * t1b;
                float t2a = accV[t][2 * half + 0] + b2v0;
                float t2b = accV[t][2 * half + 1] + b2v1;
                t2a = (t2a > 0.f) ? t2a : 0.01f * t2a;
                t2b = (t2b > 0.f) ? t2b : 0.01f * t2b;
                *(float2*)&hb[row * 132 + col] = make_float2(t1a + t2a, t1b + t2b);
            }
        }
        __syncthreads();

        // layernorm: warp handles 4 rows
        int n0 = tile * 32;
        #pragma unroll
        for (int rr = 0; rr < 4; rr++) {
            int rw = wid * 4 + rr;
            int n = n0 + rw;
            float4 h = *(float4*)&hb[rw * 132 + lane * 4];
            float s  = h.x + h.y + h.z + h.w;
            float sq = h.x * h.x + h.y * h.y + h.z * h.z + h.w * h.w;
            #pragma unroll
            for (int o = 16; o >= 1; o >>= 1) {
                s  += __shfl_xor_sync(0xffffffffu, s,  o);
                sq += __shfl_xor_sync(0xffffffffu, sq, o);
            }
            float mu  = s * (1.0f / 128.0f);
            float var = sq * (1.0f / 128.0f) - mu * mu;
            float rs  = rsqrtf(var + 1e-5f);
            if (n < NN) {
                float4 o4;
                o4.x = (h.x - mu) * rs * gv.x + bvv.x;
                o4.y = (h.y - mu) * rs * gv.y + bvv.y;
                o4.z = (h.z - mu) * rs * gv.z + bvv.z;
                o4.w = (h.w - mu) * rs * gv.w + bvv.w;
                ((float4*)out)[(size_t)n * 32 + lane] = o4;
            }
        }
        __syncthreads();   // hbuf consumed before next prefetch overwrites it
        cur ^= 1;
    }
}

// ---------------------------------------------------------------------------
extern "C" void kernel_launch(void* const* d_in, const int* in_sizes, int n_in,
                              void* d_out, int out_size) {
    const float* x     = (const float*)d_in[0];
    const float* eh_in = (const float*)d_in[1];
    const float* et_in = (const float*)d_in[2];
    const int*   tidx  = (const int*)  d_in[3];
    const float* tw    = (const float*)d_in[4];
    const float* Wh    = (const float*)d_in[5];
    const float* bh    = (const float*)d_in[6];
    const float* Wt    = (const float*)d_in[7];
    const float* bt    = (const float*)d_in[8];
    const float* W1    = (const float*)d_in[9];
    const float* b1    = (const float*)d_in[10];
    const float* W2    = (const float*)d_in[11];
    const float* b2    = (const float*)d_in[12];
    const float* gamma = (const float*)d_in[13];
    const float* beta  = (const float*)d_in[14];
    float* out = (float*)d_out;

    cudaFuncSetAttribute(k1_proj, cudaFuncAttributeMaxDynamicSharedMemorySize, K1_SMEM);
    cudaFuncSetAttribute(k3_out,  cudaFuncAttributeMaxDynamicSharedMemorySize, K3_SMEM);

    k1_proj<<<NSM, 256, K1_SMEM>>>(eh_in, et_in, Wh, bh, Wt, bt);
    k2_attn<<<NTILES, 256>>>(x, tidx, tw);
    k3_out<<<NSM, 256, K3_SMEM>>>(W1, b1, W2, b2, gamma, beta, out);
}

// round 6
// speedup vs baseline: 1.9957x; 1.0553x over previous
#include <cuda_runtime.h>
#include <cuda_bf16.h>
#include <cstdint>

#define NN     50000
#define DD     128
#define KNB    16
#define NTILES 1563    // ceil(NN/32)
#define NSM    148

// ------------------------- global scratch -----------------------------------
__device__ float         g_eh[(size_t)NN * DD];
__device__ float         g_et[(size_t)NN * DD];
__device__ __nv_bfloat16 g_uh[(size_t)NN * DD];
__device__ __nv_bfloat16 g_ul[(size_t)NN * DD];
__device__ __nv_bfloat16 g_vh[(size_t)NN * DD];
__device__ __nv_bfloat16 g_vl[(size_t)NN * DD];

// ------------------------- helpers ------------------------------------------
__device__ __forceinline__ uint32_t smem_u32(const void* p) {
    uint32_t a;
    asm("{ .reg .u64 t; cvta.to.shared.u64 t, %1; cvt.u32.u64 %0, t; }" : "=r"(a) : "l"(p));
    return a;
}
__device__ __forceinline__ uint32_t pack2(__nv_bfloat16 a, __nv_bfloat16 b) {
    __nv_bfloat162 t = __halves2bfloat162(a, b);
    return *(uint32_t*)&t;
}
__device__ __forceinline__ float tanh_fast(float z) {
    z = fminf(15.0f, fmaxf(-15.0f, z));
    float e = __expf(2.0f * z);
    return __fdividef(e - 1.0f, e + 1.0f);
}
__device__ __forceinline__ void cpa16(uint32_t dst, const void* src) {
    asm volatile("cp.async.cg.shared.global [%0], [%1], 16;" :: "r"(dst), "l"(src));
}
#define CP_COMMIT() asm volatile("cp.async.commit_group;")
#define CP_WAIT1()  asm volatile("cp.async.wait_group 1;" ::: "memory")

#define LDSM4(r0, r1, r2, r3, addr) \
    asm volatile("ldmatrix.sync.aligned.m8n8.x4.shared.b16 {%0,%1,%2,%3}, [%4];" \
        : "=r"(r0), "=r"(r1), "=r"(r2), "=r"(r3) : "r"(addr))

#define MMA_BF16(d, a0, a1, a2, a3, b0, b1) \
    asm volatile("mma.sync.aligned.m16n8k16.row.col.f32.bf16.bf16.f32 " \
        "{%0,%1,%2,%3}, {%4,%5,%6,%7}, {%8,%9}, {%0,%1,%2,%3};" \
        : "+f"((d)[0]), "+f"((d)[1]), "+f"((d)[2]), "+f"((d)[3]) \
        : "r"(a0), "r"(a1), "r"(a2), "r"(a3), "r"(b0), "r"(b1))

__device__ __forceinline__ void split4(float4 f, uint2& hv, uint2& lv) {
    __nv_bfloat16 h0 = __float2bfloat16(f.x), h1 = __float2bfloat16(f.y);
    __nv_bfloat16 h2 = __float2bfloat16(f.z), h3 = __float2bfloat16(f.w);
    hv = make_uint2(pack2(h0, h1), pack2(h2, h3));
    lv = make_uint2(
        pack2(__float2bfloat16(f.x - __bfloat162float(h0)), __float2bfloat16(f.y - __bfloat162float(h1))),
        pack2(__float2bfloat16(f.z - __bfloat162float(h2)), __float2bfloat16(f.w - __bfloat162float(h3))));
}

// split a 128x128 fp32 weight matrix into hi/lo bf16 padded smem tiles
__device__ __forceinline__ void w_split_to_smem(const float* W, char* smc,
                                                int hbase, int tid) {
    const float4* W4 = (const float4*)W;
    #pragma unroll
    for (int j = 0; j < 16; j++) {
        int i = tid + j * 256;
        int row = i >> 5, c4 = i & 31;
        uint2 hv, lv;
        split4(W4[i], hv, lv);
        uint32_t off = (uint32_t)(row * 272 + c4 * 8);
        *(uint2*)(smc + hbase + off)         = hv;
        *(uint2*)(smc + hbase + 34816 + off) = lv;
    }
}

// ------------------------- kernel 1: persistent projections -----------------
// one matrix per CTA (grid = 2*NSM): smem ~88KB -> 2 CTAs/SM
#define K1_WH 512
#define K1_WL (K1_WH + 34816)
#define K1_A  (K1_WL + 34816)      // 70144
#define K1_SMEM (K1_A + 17408)     // 87552

__global__ void __launch_bounds__(256) k1_proj(
    const float* __restrict__ eh_in, const float* __restrict__ et_in,
    const float* __restrict__ Wh, const float* __restrict__ bh,
    const float* __restrict__ Wt, const float* __restrict__ bt)
{
    extern __shared__ char smc[];
    float* smf = (float*)smc;
    const uint32_t sb = smem_u32(smc);
    const int tid = threadIdx.x, lane = tid & 31, wid = tid >> 5;
    const int mat = blockIdx.x & 1;
    const int ct0 = blockIdx.x >> 1;

    const float* in   = mat ? et_in : eh_in;
    const float* W    = mat ? Wt : Wh;
    const float* bias = mat ? bt : bh;
    float* outp       = mat ? g_et : g_eh;

    // prefetch first input tile into registers (overlaps weight conversion)
    float4 f[4];
    {
        int n0 = ct0 * 32;
        #pragma unroll
        for (int j = 0; j < 4; j++) {
            int i = tid + j * 256;
            int row = i >> 5, c4 = i & 31;
            int n = n0 + row;
            f[j] = (n < NN) ? ((const float4*)in)[(size_t)n * 32 + c4]
                            : make_float4(0.f, 0.f, 0.f, 0.f);
        }
    }

    if (tid < 128) smf[tid] = bias[tid];
    w_split_to_smem(W, smc, K1_WH, tid);

    const uint32_t Ah = sb + K1_A, Al = Ah + 8704;
    const uint32_t Bh = sb + K1_WH, Bl = sb + K1_WL;
    const int nbase = wid * 16;
    const uint32_t a_off = (uint32_t)(((lane & 7) + ((lane >> 3) & 1) * 8) * 272 + (lane >> 4) * 16);
    const uint32_t b_off = (uint32_t)((nbase + (lane >> 4) * 8 + (lane & 7)) * 272 + ((lane >> 3) & 1) * 16);
    const int r0 = lane >> 2, cs = (lane & 3) * 2;

    for (int tile = ct0; tile < NTILES; tile += NSM) {
        // convert current tile regs -> A smem tiles
        #pragma unroll
        for (int j = 0; j < 4; j++) {
            int i = tid + j * 256;
            int row = i >> 5, c4 = i & 31;
            uint2 hv, lv;
            split4(f[j], hv, lv);
            uint32_t off = (uint32_t)(row * 272 + c4 * 8);
            *(uint2*)(smc + K1_A + off)        = hv;
            *(uint2*)(smc + K1_A + 8704 + off) = lv;
        }
        // prefetch next tile
        {
            int nt = tile + NSM;
            if (nt < NTILES) {
                int n0 = nt * 32;
                #pragma unroll
                for (int j = 0; j < 4; j++) {
                    int i = tid + j * 256;
                    int row = i >> 5, c4 = i & 31;
                    int n = n0 + row;
                    f[j] = (n < NN) ? ((const float4*)in)[(size_t)n * 32 + c4]
                                    : make_float4(0.f, 0.f, 0.f, 0.f);
                }
            }
        }
        __syncthreads();

        float acc[2][2][4];
        #pragma unroll
        for (int mt = 0; mt < 2; mt++)
            #pragma unroll
            for (int t = 0; t < 2; t++) {
                acc[mt][t][0] = 0.f; acc[mt][t][1] = 0.f;
                acc[mt][t][2] = 0.f; acc[mt][t][3] = 0.f;
            }

        #pragma unroll
        for (int pass = 0; pass < 3; pass++) {
            uint32_t A = ((pass == 2) ? Al : Ah) + a_off;
            uint32_t B = ((pass == 1) ? Bl : Bh) + b_off;
            #pragma unroll
            for (int ks = 0; ks < 8; ks++) {
                uint32_t ka = ks * 32;
                uint32_t a0, a1, a2, a3, a4, a5, a6, a7;
                LDSM4(a0, a1, a2, a3, A + ka);
                LDSM4(a4, a5, a6, a7, A + ka + 16 * 272);
                uint32_t b0, b1, b2, b3;
                LDSM4(b0, b1, b2, b3, B + ka);
                MMA_BF16(acc[0][0], a0, a1, a2, a3, b0, b1);
                MMA_BF16(acc[0][1], a0, a1, a2, a3, b2, b3);
                MMA_BF16(acc[1][0], a4, a5, a6, a7, b0, b1);
                MMA_BF16(acc[1][1], a4, a5, a6, a7, b2, b3);
            }
        }

        // epilogue: bias + fp32 store
        int n0r = tile * 32;
        #pragma unroll
        for (int mt = 0; mt < 2; mt++) {
            #pragma unroll
            for (int t = 0; t < 2; t++) {
                int col = nbase + t * 8 + cs;
                float bv0 = smf[col], bv1 = smf[col + 1];
                int na = n0r + mt * 16 + r0, nb2 = na + 8;
                if (na < NN)
                    *(float2*)&outp[(size_t)na * DD + col] =
                        make_float2(acc[mt][t][0] + bv0, acc[mt][t][1] + bv1);
                if (nb2 < NN)
                    *(float2*)&outp[(size_t)nb2 * DD + col] =
                        make_float2(acc[mt][t][2] + bv0, acc[mt][t][3] + bv1);
            }
        }
        __syncthreads();
    }
}

// ------------------------- kernel 2: attention (online softmax) -------------
__global__ void __launch_bounds__(256, 3) k2_attn(
    const float* __restrict__ x, const int* __restrict__ tidx,
    const float* __restrict__ tw)
{
    const int tid = threadIdx.x, lane = tid & 31, wid = tid >> 5;
    const int n0 = blockIdx.x * 32;

    #pragma unroll 1
    for (int rr = 0; rr < 4; rr++) {
        const int n = n0 + wid * 4 + rr;
        if (n >= NN) continue;
        float4 eh = ((const float4*)g_eh)[(size_t)n * 32 + lane];
        float4 xr = ((const float4*)x)[(size_t)n * 32 + lane];

        // vectorized index/weight loads (16 each)
        int   ids[KNB];
        float ps[KNB];
        {
            const int4*   ip = (const int4*)(tidx + (size_t)n * KNB);
            const float4* pp = (const float4*)(tw + (size_t)n * KNB);
            #pragma unroll
            for (int j = 0; j < 4; j++) {
                int4 I = ip[j]; float4 P = pp[j];
                ids[4 * j + 0] = I.x; ids[4 * j + 1] = I.y;
                ids[4 * j + 2] = I.z; ids[4 * j + 3] = I.w;
                ps[4 * j + 0] = P.x; ps[4 * j + 1] = P.y;
                ps[4 * j + 2] = P.z; ps[4 * j + 3] = P.w;
            }
        }

        // online (un-shifted) softmax accumulation; depth-2 gather pipeline
        float a0 = 0.f, a1 = 0.f, a2 = 0.f, a3 = 0.f, s = 0.f;
        float4 nv0 = ((const float4*)g_et)[(size_t)ids[0] * 32 + lane];
        float4 nv1 = ((const float4*)g_et)[(size_t)ids[1] * 32 + lane];
        #pragma unroll
        for (int k = 0; k < KNB; k++) {
            float4 cur = nv0;
            nv0 = nv1;
            if (k + 2 < KNB)
                nv1 = ((const float4*)g_et)[(size_t)ids[k + 2] * 32 + lane];
            float p = ps[k], q = 2.0f - p;
            float part;
            part  = cur.x * tanh_fast(fmaf(q, eh.x, p * cur.x));
            part += cur.y * tanh_fast(fmaf(q, eh.y, p * cur.y));
            part += cur.z * tanh_fast(fmaf(q, eh.z, p * cur.z));
            part += cur.w * tanh_fast(fmaf(q, eh.w, p * cur.w));
            #pragma unroll
            for (int o = 16; o >= 1; o >>= 1)
                part += __shfl_xor_sync(0xffffffffu, part, o);
            float e = __expf(part);   // |part| ~ O(25) max; safe without shift
            a0 = fmaf(e, cur.x, a0);
            a1 = fmaf(e, cur.y, a1);
            a2 = fmaf(e, cur.z, a2);
            a3 = fmaf(e, cur.w, a3);
            s += e;
        }
        float inv = __fdividef(1.0f, s);
        float e0 = a0 * inv, e1 = a1 * inv, e2 = a2 * inv, e3 = a3 * inv;

        float4 u = make_float4(xr.x + e0, xr.y + e1, xr.z + e2, xr.w + e3);
        float4 v = make_float4(xr.x * e0, xr.y * e1, xr.z * e2, xr.w * e3);
        uint2 uhv, ulv, vhv, vlv;
        split4(u, uhv, ulv);
        split4(v, vhv, vlv);
        ((uint2*)(g_uh + (size_t)n * DD))[lane] = uhv;
        ((uint2*)(g_ul + (size_t)n * DD))[lane] = ulv;
        ((uint2*)(g_vh + (size_t)n * DD))[lane] = vhv;
        ((uint2*)(g_vl + (size_t)n * DD))[lane] = vlv;
    }
}

// ------------------------- kernel 3: persistent GEMMs + LN ------------------
#define K3_W1H 2048
#define K3_W2H 71680
#define K3_S0  141312
#define K3_S1  176128
#define K3_SMEM 210944

__device__ __forceinline__ void k3_prefetch(int tile, uint32_t stage, int tid) {
    int n0 = tile * 32;
    #pragma unroll
    for (int j = 0; j < 8; j++) {
        int i = tid + j * 256;
        int arr = i >> 9, row = (i >> 4) & 31, c = i & 15;
        int n = n0 + row;
        if (n < NN) {
            const __nv_bfloat16* src = (arr == 0) ? g_uh : (arr == 1) ? g_ul
                                      : (arr == 2) ? g_vh : g_vl;
            cpa16(stage + (uint32_t)(arr * 8704 + row * 272 + c * 16),
                  (const char*)src + ((size_t)n * 256 + (size_t)c * 16));
        }
    }
    CP_COMMIT();
}

__global__ void __launch_bounds__(256) k3_out(
    const float* __restrict__ W1, const float* __restrict__ b1,
    const float* __restrict__ W2, const float* __restrict__ b2,
    const float* __restrict__ gamma, const float* __restrict__ beta,
    float* __restrict__ out)
{
    extern __shared__ char smc[];
    float* smf = (float*)smc;
    const uint32_t sb = smem_u32(smc);
    const int tid = threadIdx.x, lane = tid & 31, wid = tid >> 5;

    k3_prefetch(blockIdx.x, sb + K3_S0, tid);

    if (tid < 128) { smf[tid] = b1[tid];       smf[256 + tid] = gamma[tid]; }
    else           { smf[tid] = b2[tid - 128]; smf[256 + tid] = beta[tid - 128]; }
    w_split_to_smem(W1, smc, K3_W1H, tid);
    w_split_to_smem(W2, smc, K3_W2H, tid);

    const int mrow0 = (wid & 1) * 16;
    const int ncol0 = (wid >> 1) * 32;
    const uint32_t a_off = (uint32_t)((mrow0 + (lane & 7) + ((lane >> 3) & 1) * 8) * 272 + (lane >> 4) * 16);
    const uint32_t b_off = (uint32_t)((ncol0 + (lane >> 4) * 8 + (lane & 7)) * 272 + ((lane >> 3) & 1) * 16);
    const int r0 = lane >> 2, cs = (lane & 3) * 2;

    float4 gv, bvv;
    gv.x  = smf[256 + lane * 4 + 0]; gv.y  = smf[256 + lane * 4 + 1];
    gv.z  = smf[256 + lane * 4 + 2]; gv.w  = smf[256 + lane * 4 + 3];
    bvv.x = smf[384 + lane * 4 + 0]; bvv.y = smf[384 + lane * 4 + 1];
    bvv.z = smf[384 + lane * 4 + 2]; bvv.w = smf[384 + lane * 4 + 3];

    int cur = 0;
    for (int tile = blockIdx.x; tile < NTILES; tile += NSM) {
        int nt = tile + NSM;
        if (nt < NTILES) k3_prefetch(nt, sb + (cur ? K3_S0 : K3_S1), tid);
        else             CP_COMMIT();
        CP_WAIT1();
        __syncthreads();

        const uint32_t S = sb + (cur ? K3_S1 : K3_S0);
        float accU[4][4], accV[4][4];
        #pragma unroll
        for (int t = 0; t < 4; t++) {
            accU[t][0] = 0.f; accU[t][1] = 0.f; accU[t][2] = 0.f; accU[t][3] = 0.f;
            accV[t][0] = 0.f; accV[t][1] = 0.f; accV[t][2] = 0.f; accV[t][3] = 0.f;
        }

        #pragma unroll
        for (int pass = 0; pass < 3; pass++) {
            uint32_t Au = S + ((pass == 2) ? 8704u : 0u) + a_off;
            uint32_t Av = Au + 17408u;
            uint32_t B1 = sb + ((pass == 1) ? (K3_W1H + 34816) : K3_W1H) + b_off;
            uint32_t B2 = sb + ((pass == 1) ? (K3_W2H + 34816) : K3_W2H) + b_off;
            #pragma unroll
            for (int ks = 0; ks < 8; ks++) {
                uint32_t ka = ks * 32;
                uint32_t u0, u1, u2, u3, v0, v1, v2, v3;
                LDSM4(u0, u1, u2, u3, Au + ka);
                LDSM4(v0, v1, v2, v3, Av + ka);
                #pragma unroll
                for (int bt = 0; bt < 2; bt++) {
                    uint32_t c0, c1, c2, c3;
                    LDSM4(c0, c1, c2, c3, B1 + ka + bt * 4352);
                    MMA_BF16(accU[2 * bt],     u0, u1, u2, u3, c0, c1);
                    MMA_BF16(accU[2 * bt + 1], u0, u1, u2, u3, c2, c3);
                    uint32_t d0, d1, d2, d3;
                    LDSM4(d0, d1, d2, d3, B2 + ka + bt * 4352);
                    MMA_BF16(accV[2 * bt],     v0, v1, v2, v3, d0, d1);
                    MMA_BF16(accV[2 * bt + 1], v0, v1, v2, v3, d2, d3);
                }
            }
        }
        __syncthreads();

        float* hb = (float*)(smc + (cur ? K3_S1 : K3_S0));
        #pragma unroll
        for (int t = 0; t < 4; t++) {
            int col = ncol0 + t * 8 + cs;
            float b1v0 = smf[col], b1v1 = smf[col + 1];
            float b2v0 = smf[128 + col], b2v1 = smf[128 + col + 1];
            #pragma unroll
            for (int half = 0; half < 2; half++) {
                int row = mrow0 + r0 + half * 8;
                float t1a = accU[t][2 * half + 0] + b1v0;
                float t1b = accU[t][2 * half + 1] + b1v1;
                t1a = (t1a > 0.f) ? t1a : 0.01f * t1a;
                t1b = (t1b > 0.f) ? t1b : 0.01f * t1b;
                float t2a = accV[t][2 * half + 0] + b2v0;
                float t2b = accV[t][2 * half + 1] + b2v1;
                t2a = (t2a > 0.f) ? t2a : 0.01f * t2a;
                t2b = (t2b > 0.f) ? t2b : 0.01f * t2b;
                *(float2*)&hb[row * 132 + col] = make_float2(t1a + t2a, t1b + t2b);
            }
        }
        __syncthreads();

        int n0r = tile * 32;
        #pragma unroll
        for (int rr = 0; rr < 4; rr++) {
            int rw = wid * 4 + rr;
            int n = n0r + rw;
            float4 h = *(float4*)&hb[rw * 132 + lane * 4];
            float s  = h.x + h.y + h.z + h.w;
            float sq = h.x * h.x + h.y * h.y + h.z * h.z + h.w * h.w;
            #pragma unroll
            for (int o = 16; o >= 1; o >>= 1) {
                s  += __shfl_xor_sync(0xffffffffu, s,  o);
                sq += __shfl_xor_sync(0xffffffffu, sq, o);
            }
            float mu  = s * (1.0f / 128.0f);
            float var = sq * (1.0f / 128.0f) - mu * mu;
            float rs  = rsqrtf(var + 1e-5f);
            if (n < NN) {
                float4 o4;
                o4.x = (h.x - mu) * rs * gv.x + bvv.x;
                o4.y = (h.y - mu) * rs * gv.y + bvv.y;
                o4.z = (h.z - mu) * rs * gv.z + bvv.z;
                o4.w = (h.w - mu) * rs * gv.w + bvv.w;
                ((float4*)out)[(size_t)n * 32 + lane] = o4;
            }
        }
        __syncthreads();
        cur ^= 1;
    }
}

// ---------------------------------------------------------------------------
extern "C" void kernel_launch(void* const* d_in, const int* in_sizes, int n_in,
                              void* d_out, int out_size) {
    const float* x     = (const float*)d_in[0];
    const float* eh_in = (const float*)d_in[1];
    const float* et_in = (const float*)d_in[2];
    const int*   tidx  = (const int*)  d_in[3];
    const float* tw    = (const float*)d_in[4];
    const float* Wh    = (const float*)d_in[5];
    const float* bh    = (const float*)d_in[6];
    const float* Wt    = (const float*)d_in[7];
    const float* bt    = (const float*)d_in[8];
    const float* W1    = (const float*)d_in[9];
    const float* b1    = (const float*)d_in[10];
    const float* W2    = (const float*)d_in[11];
    const float* b2    = (const float*)d_in[12];
    const float* gamma = (const float*)d_in[13];
    const float* beta  = (const float*)d_in[14];
    float* out = (float*)d_out;

    cudaFuncSetAttribute(k1_proj, cudaFuncAttributeMaxDynamicSharedMemorySize, K1_SMEM);
    cudaFuncSetAttribute(k3_out,  cudaFuncAttributeMaxDynamicSharedMemorySize, K3_SMEM);

    k1_proj<<<NSM * 2, 256, K1_SMEM>>>(eh_in, et_in, Wh, bh, Wt, bt);
    k2_attn<<<NTILES, 256>>>(x, tidx, tw);
    k3_out<<<NSM, 256, K3_SMEM>>>(W1, b1, W2, b2, gamma, beta, out);
}

// round 7
// speedup vs baseline: 2.3105x; 1.1577x over previous
#include <cuda_runtime.h>
#include <cuda_bf16.h>
#include <cstdint>

#define NN     50000
#define DD     128
#define KNB    16
#define NTILES 1563    // ceil(NN/32)
#define NSM    148

// ------------------------- global scratch -----------------------------------
__device__ float         g_eh[(size_t)NN * DD];
__device__ float         g_et[(size_t)NN * DD];
__device__ __nv_bfloat16 g_uh[(size_t)NN * DD];
__device__ __nv_bfloat16 g_ul[(size_t)NN * DD];
__device__ __nv_bfloat16 g_vh[(size_t)NN * DD];
__device__ __nv_bfloat16 g_vl[(size_t)NN * DD];

// ------------------------- helpers ------------------------------------------
__device__ __forceinline__ uint32_t smem_u32(const void* p) {
    uint32_t a;
    asm("{ .reg .u64 t; cvta.to.shared.u64 t, %1; cvt.u32.u64 %0, t; }" : "=r"(a) : "l"(p));
    return a;
}
__device__ __forceinline__ uint32_t pack2(__nv_bfloat16 a, __nv_bfloat16 b) {
    __nv_bfloat162 t = __halves2bfloat162(a, b);
    return *(uint32_t*)&t;
}
__device__ __forceinline__ float tanh_hw(float z) {
    float r;
    asm("tanh.approx.f32 %0, %1;" : "=f"(r) : "f"(z));
    return r;
}
__device__ __forceinline__ void cpa16(uint32_t dst, const void* src) {
    asm volatile("cp.async.cg.shared.global [%0], [%1], 16;" :: "r"(dst), "l"(src));
}
#define CP_COMMIT() asm volatile("cp.async.commit_group;")
#define CP_WAIT1()  asm volatile("cp.async.wait_group 1;" ::: "memory")

#define LDSM4(r0, r1, r2, r3, addr) \
    asm volatile("ldmatrix.sync.aligned.m8n8.x4.shared.b16 {%0,%1,%2,%3}, [%4];" \
        : "=r"(r0), "=r"(r1), "=r"(r2), "=r"(r3) : "r"(addr))

#define MMA_BF16(d, a0, a1, a2, a3, b0, b1) \
    asm volatile("mma.sync.aligned.m16n8k16.row.col.f32.bf16.bf16.f32 " \
        "{%0,%1,%2,%3}, {%4,%5,%6,%7}, {%8,%9}, {%0,%1,%2,%3};" \
        : "+f"((d)[0]), "+f"((d)[1]), "+f"((d)[2]), "+f"((d)[3]) \
        : "r"(a0), "r"(a1), "r"(a2), "r"(a3), "r"(b0), "r"(b1))

__device__ __forceinline__ void split4(float4 f, uint2& hv, uint2& lv) {
    __nv_bfloat16 h0 = __float2bfloat16(f.x), h1 = __float2bfloat16(f.y);
    __nv_bfloat16 h2 = __float2bfloat16(f.z), h3 = __float2bfloat16(f.w);
    hv = make_uint2(pack2(h0, h1), pack2(h2, h3));
    lv = make_uint2(
        pack2(__float2bfloat16(f.x - __bfloat162float(h0)), __float2bfloat16(f.y - __bfloat162float(h1))),
        pack2(__float2bfloat16(f.z - __bfloat162float(h2)), __float2bfloat16(f.w - __bfloat162float(h3))));
}

// split a 128x128 fp32 weight matrix into hi/lo bf16 padded smem tiles
__device__ __forceinline__ void w_split_to_smem(const float* W, char* smc,
                                                int hbase, int tid) {
    const float4* W4 = (const float4*)W;
    #pragma unroll
    for (int j = 0; j < 16; j++) {
        int i = tid + j * 256;
        int row = i >> 5, c4 = i & 31;
        uint2 hv, lv;
        split4(W4[i], hv, lv);
        uint32_t off = (uint32_t)(row * 272 + c4 * 8);
        *(uint2*)(smc + hbase + off)         = hv;
        *(uint2*)(smc + hbase + 34816 + off) = lv;
    }
}

// ------------------------- kernel 1: persistent projections -----------------
// one matrix per CTA (grid = 2*NSM), forced 2 CTAs/SM (regs <= 128)
#define K1_WH 512
#define K1_WL (K1_WH + 34816)
#define K1_A  (K1_WL + 34816)      // 70144
#define K1_SMEM (K1_A + 17408)     // 87552

__global__ void __launch_bounds__(256, 2) k1_proj(
    const float* __restrict__ eh_in, const float* __restrict__ et_in,
    const float* __restrict__ Wh, const float* __restrict__ bh,
    const float* __restrict__ Wt, const float* __restrict__ bt)
{
    extern __shared__ char smc[];
    float* smf = (float*)smc;
    const uint32_t sb = smem_u32(smc);
    const int tid = threadIdx.x, lane = tid & 31, wid = tid >> 5;
    const int mat = blockIdx.x & 1;
    const int ct0 = blockIdx.x >> 1;

    const float* in   = mat ? et_in : eh_in;
    const float* W    = mat ? Wt : Wh;
    const float* bias = mat ? bt : bh;
    float* outp       = mat ? g_et : g_eh;

    float4 f[4];
    {
        int n0 = ct0 * 32;
        #pragma unroll
        for (int j = 0; j < 4; j++) {
            int i = tid + j * 256;
            int row = i >> 5, c4 = i & 31;
            int n = n0 + row;
            f[j] = (n < NN) ? ((const float4*)in)[(size_t)n * 32 + c4]
                            : make_float4(0.f, 0.f, 0.f, 0.f);
        }
    }

    if (tid < 128) smf[tid] = bias[tid];
    w_split_to_smem(W, smc, K1_WH, tid);

    const uint32_t Ah = sb + K1_A, Al = Ah + 8704;
    const uint32_t Bh = sb + K1_WH, Bl = sb + K1_WL;
    const int nbase = wid * 16;
    const uint32_t a_off = (uint32_t)(((lane & 7) + ((lane >> 3) & 1) * 8) * 272 + (lane >> 4) * 16);
    const uint32_t b_off = (uint32_t)((nbase + (lane >> 4) * 8 + (lane & 7)) * 272 + ((lane >> 3) & 1) * 16);
    const int r0 = lane >> 2, cs = (lane & 3) * 2;

    for (int tile = ct0; tile < NTILES; tile += NSM) {
        #pragma unroll
        for (int j = 0; j < 4; j++) {
            int i = tid + j * 256;
            int row = i >> 5, c4 = i & 31;
            uint2 hv, lv;
            split4(f[j], hv, lv);
            uint32_t off = (uint32_t)(row * 272 + c4 * 8);
            *(uint2*)(smc + K1_A + off)        = hv;
            *(uint2*)(smc + K1_A + 8704 + off) = lv;
        }
        {
            int nt = tile + NSM;
            if (nt < NTILES) {
                int n0 = nt * 32;
                #pragma unroll
                for (int j = 0; j < 4; j++) {
                    int i = tid + j * 256;
                    int row = i >> 5, c4 = i & 31;
                    int n = n0 + row;
                    f[j] = (n < NN) ? ((const float4*)in)[(size_t)n * 32 + c4]
                                    : make_float4(0.f, 0.f, 0.f, 0.f);
                }
            }
        }
        __syncthreads();

        float acc[2][2][4];
        #pragma unroll
        for (int mt = 0; mt < 2; mt++)
            #pragma unroll
            for (int t = 0; t < 2; t++) {
                acc[mt][t][0] = 0.f; acc[mt][t][1] = 0.f;
                acc[mt][t][2] = 0.f; acc[mt][t][3] = 0.f;
            }

        #pragma unroll
        for (int pass = 0; pass < 3; pass++) {
            uint32_t A = ((pass == 2) ? Al : Ah) + a_off;
            uint32_t B = ((pass == 1) ? Bl : Bh) + b_off;
            #pragma unroll
            for (int ks = 0; ks < 8; ks++) {
                uint32_t ka = ks * 32;
                uint32_t a0, a1, a2, a3, a4, a5, a6, a7;
                LDSM4(a0, a1, a2, a3, A + ka);
                LDSM4(a4, a5, a6, a7, A + ka + 16 * 272);
                uint32_t b0, b1, b2, b3;
                LDSM4(b0, b1, b2, b3, B + ka);
                MMA_BF16(acc[0][0], a0, a1, a2, a3, b0, b1);
                MMA_BF16(acc[0][1], a0, a1, a2, a3, b2, b3);
                MMA_BF16(acc[1][0], a4, a5, a6, a7, b0, b1);
                MMA_BF16(acc[1][1], a4, a5, a6, a7, b2, b3);
            }
        }

        int n0r = tile * 32;
        #pragma unroll
        for (int mt = 0; mt < 2; mt++) {
            #pragma unroll
            for (int t = 0; t < 2; t++) {
                int col = nbase + t * 8 + cs;
                float bv0 = smf[col], bv1 = smf[col + 1];
                int na = n0r + mt * 16 + r0, nb2 = na + 8;
                if (na < NN)
                    *(float2*)&outp[(size_t)na * DD + col] =
                        make_float2(acc[mt][t][0] + bv0, acc[mt][t][1] + bv1);
                if (nb2 < NN)
                    *(float2*)&outp[(size_t)nb2 * DD + col] =
                        make_float2(acc[mt][t][2] + bv0, acc[mt][t][3] + bv1);
            }
        }
        __syncthreads();
    }
}

// ------------------------- kernel 2: attention (hw tanh) --------------------
__global__ void __launch_bounds__(256, 3) k2_attn(
    const float* __restrict__ x, const int* __restrict__ tidx,
    const float* __restrict__ tw)
{
    const int tid = threadIdx.x, lane = tid & 31, wid = tid >> 5;
    const int n0 = blockIdx.x * 32;

    #pragma unroll 1
    for (int rr = 0; rr < 4; rr++) {
        const int n = n0 + wid * 4 + rr;
        if (n >= NN) continue;
        float4 eh = ((const float4*)g_eh)[(size_t)n * 32 + lane];
        float4 xr = ((const float4*)x)[(size_t)n * 32 + lane];

        int   ids[KNB];
        float ps[KNB];
        {
            const int4*   ip = (const int4*)(tidx + (size_t)n * KNB);
            const float4* pp = (const float4*)(tw + (size_t)n * KNB);
            #pragma unroll
            for (int j = 0; j < 4; j++) {
                int4 I = ip[j]; float4 P = pp[j];
                ids[4 * j + 0] = I.x; ids[4 * j + 1] = I.y;
                ids[4 * j + 2] = I.z; ids[4 * j + 3] = I.w;
                ps[4 * j + 0] = P.x; ps[4 * j + 1] = P.y;
                ps[4 * j + 2] = P.z; ps[4 * j + 3] = P.w;
            }
        }

        float a0 = 0.f, a1 = 0.f, a2 = 0.f, a3 = 0.f, s = 0.f;
        float4 nv0 = ((const float4*)g_et)[(size_t)ids[0] * 32 + lane];
        float4 nv1 = ((const float4*)g_et)[(size_t)ids[1] * 32 + lane];
        #pragma unroll
        for (int k = 0; k < KNB; k++) {
            float4 cur = nv0;
            nv0 = nv1;
            if (k + 2 < KNB)
                nv1 = ((const float4*)g_et)[(size_t)ids[k + 2] * 32 + lane];
            float p = ps[k], q = 2.0f - p;
            float part;
            part  = cur.x * tanh_hw(fmaf(q, eh.x, p * cur.x));
            part += cur.y * tanh_hw(fmaf(q, eh.y, p * cur.y));
            part += cur.z * tanh_hw(fmaf(q, eh.z, p * cur.z));
            part += cur.w * tanh_hw(fmaf(q, eh.w, p * cur.w));
            #pragma unroll
            for (int o = 16; o >= 1; o >>= 1)
                part += __shfl_xor_sync(0xffffffffu, part, o);
            float e = __expf(part);   // |part| bounded ~25; safe without shift
            a0 = fmaf(e, cur.x, a0);
            a1 = fmaf(e, cur.y, a1);
            a2 = fmaf(e, cur.z, a2);
            a3 = fmaf(e, cur.w, a3);
            s += e;
        }
        float inv = __fdividef(1.0f, s);
        float e0 = a0 * inv, e1 = a1 * inv, e2 = a2 * inv, e3 = a3 * inv;

        float4 u = make_float4(xr.x + e0, xr.y + e1, xr.z + e2, xr.w + e3);
        float4 v = make_float4(xr.x * e0, xr.y * e1, xr.z * e2, xr.w * e3);
        uint2 uhv, ulv, vhv, vlv;
        split4(u, uhv, ulv);
        split4(v, vhv, vlv);
        ((uint2*)(g_uh + (size_t)n * DD))[lane] = uhv;
        ((uint2*)(g_ul + (size_t)n * DD))[lane] = ulv;
        ((uint2*)(g_vh + (size_t)n * DD))[lane] = vhv;
        ((uint2*)(g_vl + (size_t)n * DD))[lane] = vlv;
    }
}

// ------------------------- kernel 3: persistent GEMMs + LN ------------------
#define K3_W1H 2048
#define K3_W2H 71680
#define K3_S0  141312
#define K3_S1  176128
#define K3_SMEM 210944

__device__ __forceinline__ void k3_prefetch(int tile, uint32_t stage, int tid) {
    int n0 = tile * 32;
    #pragma unroll
    for (int j = 0; j < 8; j++) {
        int i = tid + j * 256;
        int arr = i >> 9, row = (i >> 4) & 31, c = i & 15;
        int n = n0 + row;
        if (n < NN) {
            const __nv_bfloat16* src = (arr == 0) ? g_uh : (arr == 1) ? g_ul
                                      : (arr == 2) ? g_vh : g_vl;
            cpa16(stage + (uint32_t)(arr * 8704 + row * 272 + c * 16),
                  (const char*)src + ((size_t)n * 256 + (size_t)c * 16));
        }
    }
    CP_COMMIT();
}

__global__ void __launch_bounds__(256) k3_out(
    const float* __restrict__ W1, const float* __restrict__ b1,
    const float* __restrict__ W2, const float* __restrict__ b2,
    const float* __restrict__ gamma, const float* __restrict__ beta,
    float* __restrict__ out)
{
    extern __shared__ char smc[];
    float* smf = (float*)smc;
    const uint32_t sb = smem_u32(smc);
    const int tid = threadIdx.x, lane = tid & 31, wid = tid >> 5;

    k3_prefetch(blockIdx.x, sb + K3_S0, tid);

    if (tid < 128) { smf[tid] = b1[tid];       smf[256 + tid] = gamma[tid]; }
    else           { smf[tid] = b2[tid - 128]; smf[256 + tid] = beta[tid - 128]; }
    w_split_to_smem(W1, smc, K3_W1H, tid);
    w_split_to_smem(W2, smc, K3_W2H, tid);

    const int mrow0 = (wid & 1) * 16;
    const int ncol0 = (wid >> 1) * 32;
    const uint32_t a_off = (uint32_t)((mrow0 + (lane & 7) + ((lane >> 3) & 1) * 8) * 272 + (lane >> 4) * 16);
    const uint32_t b_off = (uint32_t)((ncol0 + (lane >> 4) * 8 + (lane & 7)) * 272 + ((lane >> 3) & 1) * 16);
    const int r0 = lane >> 2, cs = (lane & 3) * 2;

    float4 gv, bvv;
    gv.x  = smf[256 + lane * 4 + 0]; gv.y  = smf[256 + lane * 4 + 1];
    gv.z  = smf[256 + lane * 4 + 2]; gv.w  = smf[256 + lane * 4 + 3];
    bvv.x = smf[384 + lane * 4 + 0]; bvv.y = smf[384 + lane * 4 + 1];
    bvv.z = smf[384 + lane * 4 + 2]; bvv.w = smf[384 + lane * 4 + 3];

    int cur = 0;
    for (int tile = blockIdx.x; tile < NTILES; tile += NSM) {
        int nt = tile + NSM;
        if (nt < NTILES) k3_prefetch(nt, sb + (cur ? K3_S0 : K3_S1), tid);
        else             CP_COMMIT();
        CP_WAIT1();
        __syncthreads();

        const uint32_t S = sb + (cur ? K3_S1 : K3_S0);
        float accU[4][4], accV[4][4];
        #pragma unroll
        for (int t = 0; t < 4; t++) {
            accU[t][0] = 0.f; accU[t][1] = 0.f; accU[t][2] = 0.f; accU[t][3] = 0.f;
            accV[t][0] = 0.f; accV[t][1] = 0.f; accV[t][2] = 0.f; accV[t][3] = 0.f;
        }

        #pragma unroll
        for (int pass = 0; pass < 3; pass++) {
            uint32_t Au = S + ((pass == 2) ? 8704u : 0u) + a_off;
            uint32_t Av = Au + 17408u;
            uint32_t B1 = sb + ((pass == 1) ? (K3_W1H + 34816) : K3_W1H) + b_off;
            uint32_t B2 = sb + ((pass == 1) ? (K3_W2H + 34816) : K3_W2H) + b_off;
            #pragma unroll
            for (int ks = 0; ks < 8; ks++) {
                uint32_t ka = ks * 32;
                uint32_t u0, u1, u2, u3, v0, v1, v2, v3;
                LDSM4(u0, u1, u2, u3, Au + ka);
                LDSM4(v0, v1, v2, v3, Av + ka);
                #pragma unroll
                for (int bt = 0; bt < 2; bt++) {
                    uint32_t c0, c1, c2, c3;
                    LDSM4(c0, c1, c2, c3, B1 + ka + bt * 4352);
                    MMA_BF16(accU[2 * bt],     u0, u1, u2, u3, c0, c1);
                    MMA_BF16(accU[2 * bt + 1], u0, u1, u2, u3, c2, c3);
                    uint32_t d0, d1, d2, d3;
                    LDSM4(d0, d1, d2, d3, B2 + ka + bt * 4352);
                    MMA_BF16(accV[2 * bt],     v0, v1, v2, v3, d0, d1);
                    MMA_BF16(accV[2 * bt + 1], v0, v1, v2, v3, d2, d3);
                }
            }
        }
        __syncthreads();

        float* hb = (float*)(smc + (cur ? K3_S1 : K3_S0));
        #pragma unroll
        for (int t = 0; t < 4; t++) {
            int col = ncol0 + t * 8 + cs;
            float b1v0 = smf[col], b1v1 = smf[col + 1];
            float b2v0 = smf[128 + col], b2v1 = smf[128 + col + 1];
            #pragma unroll
            for (int half = 0; half < 2; half++) {
                int row = mrow0 + r0 + half * 8;
                float t1a = accU[t][2 * half + 0] + b1v0;
                float t1b = accU[t][2 * half + 1] + b1v1;
                t1a = (t1a > 0.f) ? t1a : 0.01f * t1a;
                t1b = (t1b > 0.f) ? t1b : 0.01f * t1b;
                float t2a = accV[t][2 * half + 0] + b2v0;
                float t2b = accV[t][2 * half + 1] + b2v1;
                t2a = (t2a > 0.f) ? t2a : 0.01f * t2a;
                t2b = (t2b > 0.f) ? t2b : 0.01f * t2b;
                *(float2*)&hb[row * 132 + col] = make_float2(t1a + t2a, t1b + t2b);
            }
        }
        __syncthreads();

        int n0r = tile * 32;
        #pragma unroll
        for (int rr = 0; rr < 4; rr++) {
            int rw = wid * 4 + rr;
            int n = n0r + rw;
            float4 h = *(float4*)&hb[rw * 132 + lane * 4];
            float s  = h.x + h.y + h.z + h.w;
            float sq = h.x * h.x + h.y * h.y + h.z * h.z + h.w * h.w;
            #pragma unroll
            for (int o = 16; o >= 1; o >>= 1) {
                s  += __shfl_xor_sync(0xffffffffu, s,  o);
                sq += __shfl_xor_sync(0xffffffffu, sq, o);
            }
            float mu  = s * (1.0f / 128.0f);
            float var = sq * (1.0f / 128.0f) - mu * mu;
            float rs  = rsqrtf(var + 1e-5f);
            if (n < NN) {
                float4 o4;
                o4.x = (h.x - mu) * rs * gv.x + bvv.x;
                o4.y = (h.y - mu) * rs * gv.y + bvv.y;
                o4.z = (h.z - mu) * rs * gv.z + bvv.z;
                o4.w = (h.w - mu) * rs * gv.w + bvv.w;
                ((float4*)out)[(size_t)n * 32 + lane] = o4;
            }
        }
        __syncthreads();
        cur ^= 1;
    }
}

// ---------------------------------------------------------------------------
extern "C" void kernel_launch(void* const* d_in, const int* in_sizes, int n_in,
                              void* d_out, int out_size) {
    const float* x     = (const float*)d_in[0];
    const float* eh_in = (const float*)d_in[1];
    const float* et_in = (const float*)d_in[2];
    const int*   tidx  = (const int*)  d_in[3];
    const float* tw    = (const float*)d_in[4];
    const float* Wh    = (const float*)d_in[5];
    const float* bh    = (const float*)d_in[6];
    const float* Wt    = (const float*)d_in[7];
    const float* bt    = (const float*)d_in[8];
    const float* W1    = (const float*)d_in[9];
    const float* b1    = (const float*)d_in[10];
    const float* W2    = (const float*)d_in[11];
    const float* b2    = (const float*)d_in[12];
    const float* gamma = (const float*)d_in[13];
    const float* beta  = (const float*)d_in[14];
    float* out = (float*)d_out;

    cudaFuncSetAttribute(k1_proj, cudaFuncAttributeMaxDynamicSharedMemorySize, K1_SMEM);
    cudaFuncSetAttribute(k3_out,  cudaFuncAttributeMaxDynamicSharedMemorySize, K3_SMEM);

    k1_proj<<<NSM * 2, 256, K1_SMEM>>>(eh_in, et_in, Wh, bh, Wt, bt);
    k2_attn<<<NTILES, 256>>>(x, tidx, tw);
    k3_out<<<NSM, 256, K3_SMEM>>>(W1, b1, W2, b2, gamma, beta, out);
}

// round 8
// speedup vs baseline: 2.3678x; 1.0248x over previous
#include <cuda_runtime.h>
#include <cuda_bf16.h>
#include <cstdint>

#define NN     50000
#define DD     128
#define KNB    16
#define NTILES 1563    // ceil(NN/32)
#define NSM    148

// ------------------------- global scratch -----------------------------------
__device__ float         g_eh[(size_t)NN * DD];
__device__ float         g_et[(size_t)NN * DD];
__device__ __nv_bfloat16 g_uh[(size_t)NN * DD];
__device__ __nv_bfloat16 g_ul[(size_t)NN * DD];
__device__ __nv_bfloat16 g_vh[(size_t)NN * DD];
__device__ __nv_bfloat16 g_vl[(size_t)NN * DD];

// ------------------------- helpers ------------------------------------------
__device__ __forceinline__ uint32_t smem_u32(const void* p) {
    uint32_t a;
    asm("{ .reg .u64 t; cvta.to.shared.u64 t, %1; cvt.u32.u64 %0, t; }" : "=r"(a) : "l"(p));
    return a;
}
__device__ __forceinline__ uint32_t pack2(__nv_bfloat16 a, __nv_bfloat16 b) {
    __nv_bfloat162 t = __halves2bfloat162(a, b);
    return *(uint32_t*)&t;
}
__device__ __forceinline__ float tanh_hw(float z) {
    float r;
    asm("tanh.approx.f32 %0, %1;" : "=f"(r) : "f"(z));
    return r;
}
__device__ __forceinline__ void cpa16(uint32_t dst, const void* src) {
    asm volatile("cp.async.cg.shared.global [%0], [%1], 16;" :: "r"(dst), "l"(src));
}
#define CP_COMMIT() asm volatile("cp.async.commit_group;")
#define CP_WAIT0()  asm volatile("cp.async.wait_group 0;" ::: "memory")
#define CP_WAIT1()  asm volatile("cp.async.wait_group 1;" ::: "memory")

#define LDSM4(r0, r1, r2, r3, addr) \
    asm volatile("ldmatrix.sync.aligned.m8n8.x4.shared.b16 {%0,%1,%2,%3}, [%4];" \
        : "=r"(r0), "=r"(r1), "=r"(r2), "=r"(r3) : "r"(addr))

#define MMA_BF16(d, a0, a1, a2, a3, b0, b1) \
    asm volatile("mma.sync.aligned.m16n8k16.row.col.f32.bf16.bf16.f32 " \
        "{%0,%1,%2,%3}, {%4,%5,%6,%7}, {%8,%9}, {%0,%1,%2,%3};" \
        : "+f"((d)[0]), "+f"((d)[1]), "+f"((d)[2]), "+f"((d)[3]) \
        : "r"(a0), "r"(a1), "r"(a2), "r"(a3), "r"(b0), "r"(b1))

__device__ __forceinline__ void split4(float4 f, uint2& hv, uint2& lv) {
    __nv_bfloat16 h0 = __float2bfloat16(f.x), h1 = __float2bfloat16(f.y);
    __nv_bfloat16 h2 = __float2bfloat16(f.z), h3 = __float2bfloat16(f.w);
    hv = make_uint2(pack2(h0, h1), pack2(h2, h3));
    lv = make_uint2(
        pack2(__float2bfloat16(f.x - __bfloat162float(h0)), __float2bfloat16(f.y - __bfloat162float(h1))),
        pack2(__float2bfloat16(f.z - __bfloat162float(h2)), __float2bfloat16(f.w - __bfloat162float(h3))));
}

// split a 128x128 fp32 weight matrix into hi/lo bf16 padded smem tiles
__device__ __forceinline__ void w_split_to_smem(const float* W, char* smc,
                                                int hbase, int tid) {
    const float4* W4 = (const float4*)W;
    #pragma unroll
    for (int j = 0; j < 16; j++) {
        int i = tid + j * 256;
        int row = i >> 5, c4 = i & 31;
        uint2 hv, lv;
        split4(W4[i], hv, lv);
        uint32_t off = (uint32_t)(row * 272 + c4 * 8);
        *(uint2*)(smc + hbase + off)         = hv;
        *(uint2*)(smc + hbase + 34816 + off) = lv;
    }
}

// ------------------------- kernel 1: persistent projections -----------------
// one matrix per CTA (grid = 2*NSM), 2 CTAs/SM; input staged via cp.async
#define K1_WH   512
#define K1_WL   (K1_WH + 34816)
#define K1_A    (K1_WL + 34816)     // 70144: Ah, then Al at +8704
#define K1_STG  (K1_A + 17408)      // 87552: fp32 stage, 32 rows x 512 B
#define K1_SMEM (K1_STG + 16384)    // 103936  -> 2 CTAs/SM (<= 114688)

__global__ void __launch_bounds__(256, 2) k1_proj(
    const float* __restrict__ eh_in, const float* __restrict__ et_in,
    const float* __restrict__ Wh, const float* __restrict__ bh,
    const float* __restrict__ Wt, const float* __restrict__ bt)
{
    extern __shared__ char smc[];
    float* smf = (float*)smc;
    const uint32_t sb = smem_u32(smc);
    const int tid = threadIdx.x, lane = tid & 31, wid = tid >> 5;
    const int mat = blockIdx.x & 1;
    const int ct0 = blockIdx.x >> 1;

    const float* in   = mat ? et_in : eh_in;
    const float* W    = mat ? Wt : Wh;
    const float* bias = mat ? bt : bh;
    float* outp       = mat ? g_et : g_eh;

    // issue cp.async for first tile into stage (4 chunks of 16B per thread)
    {
        int n0 = ct0 * 32;
        #pragma unroll
        for (int j = 0; j < 4; j++) {
            int i = tid + j * 256;           // chunk id: row = i>>5, c = i&31
            int row = i >> 5, c = i & 31;
            int n = n0 + row;
            uint32_t d = sb + K1_STG + (uint32_t)(row * 512 + c * 16);
            if (n < NN) cpa16(d, (const char*)in + ((size_t)n * 512 + (size_t)c * 16));
            else        *(uint4*)(smc + K1_STG + row * 512 + c * 16) = make_uint4(0u,0u,0u,0u);
        }
        CP_COMMIT();
    }

    if (tid < 128) smf[tid] = bias[tid];
    w_split_to_smem(W, smc, K1_WH, tid);   // overlaps in-flight cp.async

    const uint32_t Ah = sb + K1_A, Al = Ah + 8704;
    const uint32_t Bh = sb + K1_WH, Bl = sb + K1_WL;
    const int nbase = wid * 16;
    const uint32_t a_off = (uint32_t)(((lane & 7) + ((lane >> 3) & 1) * 8) * 272 + (lane >> 4) * 16);
    const uint32_t b_off = (uint32_t)((nbase + (lane >> 4) * 8 + (lane & 7)) * 272 + ((lane >> 3) & 1) * 16);
    const int r0 = lane >> 2, cs = (lane & 3) * 2;

    for (int tile = ct0; tile < NTILES; tile += NSM) {
        CP_WAIT0();
        __syncthreads();                   // stage ready; prev gemm reads of Ah/Al done

        // convert stage(fp32) -> Ah/Al (split bf16)
        #pragma unroll
        for (int j = 0; j < 4; j++) {
            int i = tid + j * 256;
            int row = i >> 5, c4 = i & 31;
            float4 f = *(const float4*)(smc + K1_STG + row * 512 + c4 * 16);
            uint2 hv, lv;
            split4(f, hv, lv);
            uint32_t off = (uint32_t)(row * 272 + c4 * 8);
            *(uint2*)(smc + K1_A + off)        = hv;
            *(uint2*)(smc + K1_A + 8704 + off) = lv;
        }
        __syncthreads();                   // convert reads/writes complete

        // issue cp.async for next tile (overlaps gemm + epilogue)
        {
            int nt = tile + NSM;
            if (nt < NTILES) {
                int n0 = nt * 32;
                #pragma unroll
                for (int j = 0; j < 4; j++) {
                    int i = tid + j * 256;
                    int row = i >> 5, c = i & 31;
                    int n = n0 + row;
                    uint32_t d = sb + K1_STG + (uint32_t)(row * 512 + c * 16);
                    if (n < NN) cpa16(d, (const char*)in + ((size_t)n * 512 + (size_t)c * 16));
                    else        *(uint4*)(smc + K1_STG + row * 512 + c * 16) = make_uint4(0u,0u,0u,0u);
                }
            }
            CP_COMMIT();
        }

        float acc[2][2][4];
        #pragma unroll
        for (int mt = 0; mt < 2; mt++)
            #pragma unroll
            for (int t = 0; t < 2; t++) {
                acc[mt][t][0] = 0.f; acc[mt][t][1] = 0.f;
                acc[mt][t][2] = 0.f; acc[mt][t][3] = 0.f;
            }

        #pragma unroll
        for (int pass = 0; pass < 3; pass++) {
            uint32_t A = ((pass == 2) ? Al : Ah) + a_off;
            uint32_t B = ((pass == 1) ? Bl : Bh) + b_off;
            #pragma unroll
            for (int ks = 0; ks < 8; ks++) {
                uint32_t ka = ks * 32;
                uint32_t a0, a1, a2, a3, a4, a5, a6, a7;
                LDSM4(a0, a1, a2, a3, A + ka);
                LDSM4(a4, a5, a6, a7, A + ka + 16 * 272);
                uint32_t b0, b1, b2, b3;
                LDSM4(b0, b1, b2, b3, B + ka);
                MMA_BF16(acc[0][0], a0, a1, a2, a3, b0, b1);
                MMA_BF16(acc[0][1], a0, a1, a2, a3, b2, b3);
                MMA_BF16(acc[1][0], a4, a5, a6, a7, b0, b1);
                MMA_BF16(acc[1][1], a4, a5, a6, a7, b2, b3);
            }
        }

        int n0r = tile * 32;
        #pragma unroll
        for (int mt = 0; mt < 2; mt++) {
            #pragma unroll
            for (int t = 0; t < 2; t++) {
                int col = nbase + t * 8 + cs;
                float bv0 = smf[col], bv1 = smf[col + 1];
                int na = n0r + mt * 16 + r0, nb2 = na + 8;
                if (na < NN)
                    *(float2*)&outp[(size_t)na * DD + col] =
                        make_float2(acc[mt][t][0] + bv0, acc[mt][t][1] + bv1);
                if (nb2 < NN)
                    *(float2*)&outp[(size_t)nb2 * DD + col] =
                        make_float2(acc[mt][t][2] + bv0, acc[mt][t][3] + bv1);
            }
        }
    }
}

// ------------------------- kernel 2: attention (hw tanh) --------------------
__global__ void __launch_bounds__(256, 3) k2_attn(
    const float* __restrict__ x, const int* __restrict__ tidx,
    const float* __restrict__ tw)
{
    const int tid = threadIdx.x, lane = tid & 31, wid = tid >> 5;
    const int n0 = blockIdx.x * 32;

    #pragma unroll 1
    for (int rr = 0; rr < 4; rr++) {
        const int n = n0 + wid * 4 + rr;
        if (n >= NN) continue;
        float4 eh = ((const float4*)g_eh)[(size_t)n * 32 + lane];
        float4 xr = ((const float4*)x)[(size_t)n * 32 + lane];

        int   ids[KNB];
        float ps[KNB];
        {
            const int4*   ip = (const int4*)(tidx + (size_t)n * KNB);
            const float4* pp = (const float4*)(tw + (size_t)n * KNB);
            #pragma unroll
            for (int j = 0; j < 4; j++) {
                int4 I = ip[j]; float4 P = pp[j];
                ids[4 * j + 0] = I.x; ids[4 * j + 1] = I.y;
                ids[4 * j + 2] = I.z; ids[4 * j + 3] = I.w;
                ps[4 * j + 0] = P.x; ps[4 * j + 1] = P.y;
                ps[4 * j + 2] = P.z; ps[4 * j + 3] = P.w;
            }
        }

        float a0 = 0.f, a1 = 0.f, a2 = 0.f, a3 = 0.f, s = 0.f;
        float4 nv0 = ((const float4*)g_et)[(size_t)ids[0] * 32 + lane];
        float4 nv1 = ((const float4*)g_et)[(size_t)ids[1] * 32 + lane];
        #pragma unroll
        for (int k = 0; k < KNB; k++) {
            float4 cur = nv0;
            nv0 = nv1;
            if (k + 2 < KNB)
                nv1 = ((const float4*)g_et)[(size_t)ids[k + 2] * 32 + lane];
            float p = ps[k], q = 2.0f - p;
            float part;
            part  = cur.x * tanh_hw(fmaf(q, eh.x, p * cur.x));
            part += cur.y * tanh_hw(fmaf(q, eh.y, p * cur.y));
            part += cur.z * tanh_hw(fmaf(q, eh.z, p * cur.z));
            part += cur.w * tanh_hw(fmaf(q, eh.w, p * cur.w));
            #pragma unroll
            for (int o = 16; o >= 1; o >>= 1)
                part += __shfl_xor_sync(0xffffffffu, part, o);
            float e = __expf(part);
            a0 = fmaf(e, cur.x, a0);
            a1 = fmaf(e, cur.y, a1);
            a2 = fmaf(e, cur.z, a2);
            a3 = fmaf(e, cur.w, a3);
            s += e;
        }
        float inv = __fdividef(1.0f, s);
        float e0 = a0 * inv, e1 = a1 * inv, e2 = a2 * inv, e3 = a3 * inv;

        float4 u = make_float4(xr.x + e0, xr.y + e1, xr.z + e2, xr.w + e3);
        float4 v = make_float4(xr.x * e0, xr.y * e1, xr.z * e2, xr.w * e3);
        uint2 uhv, ulv, vhv, vlv;
        split4(u, uhv, ulv);
        split4(v, vhv, vlv);
        ((uint2*)(g_uh + (size_t)n * DD))[lane] = uhv;
        ((uint2*)(g_ul + (size_t)n * DD))[lane] = ulv;
        ((uint2*)(g_vh + (size_t)n * DD))[lane] = vhv;
        ((uint2*)(g_vl + (size_t)n * DD))[lane] = vlv;
    }
}

// ------------------------- kernel 3: persistent GEMMs + LN ------------------
#define K3_W1H 2048
#define K3_W2H 71680
#define K3_S0  141312
#define K3_S1  176128
#define K3_SMEM 210944

__device__ __forceinline__ void k3_prefetch(int tile, uint32_t stage, int tid) {
    int n0 = tile * 32;
    #pragma unroll
    for (int j = 0; j < 8; j++) {
        int i = tid + j * 256;
        int arr = i >> 9, row = (i >> 4) & 31, c = i & 15;
        int n = n0 + row;
        if (n < NN) {
            const __nv_bfloat16* src = (arr == 0) ? g_uh : (arr == 1) ? g_ul
                                      : (arr == 2) ? g_vh : g_vl;
            cpa16(stage + (uint32_t)(arr * 8704 + row * 272 + c * 16),
                  (const char*)src + ((size_t)n * 256 + (size_t)c * 16));
        }
    }
    CP_COMMIT();
}

__global__ void __launch_bounds__(256) k3_out(
    const float* __restrict__ W1, const float* __restrict__ b1,
    const float* __restrict__ W2, const float* __restrict__ b2,
    const float* __restrict__ gamma, const float* __restrict__ beta,
    float* __restrict__ out)
{
    extern __shared__ char smc[];
    float* smf = (float*)smc;
    const uint32_t sb = smem_u32(smc);
    const int tid = threadIdx.x, lane = tid & 31, wid = tid >> 5;

    k3_prefetch(blockIdx.x, sb + K3_S0, tid);

    if (tid < 128) { smf[tid] = b1[tid];       smf[256 + tid] = gamma[tid]; }
    else           { smf[tid] = b2[tid - 128]; smf[256 + tid] = beta[tid - 128]; }
    w_split_to_smem(W1, smc, K3_W1H, tid);
    w_split_to_smem(W2, smc, K3_W2H, tid);

    const int mrow0 = (wid & 1) * 16;
    const int ncol0 = (wid >> 1) * 32;
    const uint32_t a_off = (uint32_t)((mrow0 + (lane & 7) + ((lane >> 3) & 1) * 8) * 272 + (lane >> 4) * 16);
    const uint32_t b_off = (uint32_t)((ncol0 + (lane >> 4) * 8 + (lane & 7)) * 272 + ((lane >> 3) & 1) * 16);
    const int r0 = lane >> 2, cs = (lane & 3) * 2;

    float4 gv, bvv;
    gv.x  = smf[256 + lane * 4 + 0]; gv.y  = smf[256 + lane * 4 + 1];
    gv.z  = smf[256 + lane * 4 + 2]; gv.w  = smf[256 + lane * 4 + 3];
    bvv.x = smf[384 + lane * 4 + 0]; bvv.y = smf[384 + lane * 4 + 1];
    bvv.z = smf[384 + lane * 4 + 2]; bvv.w = smf[384 + lane * 4 + 3];

    int cur = 0;
    for (int tile = blockIdx.x; tile < NTILES; tile += NSM) {
        int nt = tile + NSM;
        if (nt < NTILES) k3_prefetch(nt, sb + (cur ? K3_S0 : K3_S1), tid);
        else             CP_COMMIT();
        CP_WAIT1();
        __syncthreads();

        const uint32_t S = sb + (cur ? K3_S1 : K3_S0);
        float accU[4][4], accV[4][4];
        #pragma unroll
        for (int t = 0; t < 4; t++) {
            accU[t][0] = 0.f; accU[t][1] = 0.f; accU[t][2] = 0.f; accU[t][3] = 0.f;
            accV[t][0] = 0.f; accV[t][1] = 0.f; accV[t][2] = 0.f; accV[t][3] = 0.f;
        }

        #pragma unroll
        for (int pass = 0; pass < 3; pass++) {
            uint32_t Au = S + ((pass == 2) ? 8704u : 0u) + a_off;
            uint32_t Av = Au + 17408u;
            uint32_t B1 = sb + ((pass == 1) ? (K3_W1H + 34816) : K3_W1H) + b_off;
            uint32_t B2 = sb + ((pass == 1) ? (K3_W2H + 34816) : K3_W2H) + b_off;
            #pragma unroll
            for (int ks = 0; ks < 8; ks++) {
                uint32_t ka = ks * 32;
                uint32_t u0, u1, u2, u3, v0, v1, v2, v3;
                LDSM4(u0, u1, u2, u3, Au + ka);
                LDSM4(v0, v1, v2, v3, Av + ka);
                #pragma unroll
                for (int bt = 0; bt < 2; bt++) {
                    uint32_t c0, c1, c2, c3;
                    LDSM4(c0, c1, c2, c3, B1 + ka + bt * 4352);
                    MMA_BF16(accU[2 * bt],     u0, u1, u2, u3, c0, c1);
                    MMA_BF16(accU[2 * bt + 1], u0, u1, u2, u3, c2, c3);
                    uint32_t d0, d1, d2, d3;
                    LDSM4(d0, d1, d2, d3, B2 + ka + bt * 4352);
                    MMA_BF16(accV[2 * bt],     v0, v1, v2, v3, d0, d1);
                    MMA_BF16(accV[2 * bt + 1], v0, v1, v2, v3, d2, d3);
                }
            }
        }
        __syncthreads();

        float* hb = (float*)(smc + (cur ? K3_S1 : K3_S0));
        #pragma unroll
        for (int t = 0; t < 4; t++) {
            int col = ncol0 + t * 8 + cs;
            float b1v0 = smf[col], b1v1 = smf[col + 1];
            float b2v0 = smf[128 + col], b2v1 = smf[128 + col + 1];
            #pragma unroll
            for (int half = 0; half < 2; half++) {
                int row = mrow0 + r0 + half * 8;
                float t1a = accU[t][2 * half + 0] + b1v0;
                float t1b = accU[t][2 * half + 1] + b1v1;
                t1a = (t1a > 0.f) ? t1a : 0.01f * t1a;
                t1b = (t1b > 0.f) ? t1b : 0.01f * t1b;
                float t2a = accV[t][2 * half + 0] + b2v0;
                float t2b = accV[t][2 * half + 1] + b2v1;
                t2a = (t2a > 0.f) ? t2a : 0.01f * t2a;
                t2b = (t2b > 0.f) ? t2b : 0.01f * t2b;
                *(float2*)&hb[row * 132 + col] = make_float2(t1a + t2a, t1b + t2b);
            }
        }
        __syncthreads();

        int n0r = tile * 32;
        #pragma unroll
        for (int rr = 0; rr < 4; rr++) {
            int rw = wid * 4 + rr;
            int n = n0r + rw;
            float4 h = *(float4*)&hb[rw * 132 + lane * 4];
            float s  = h.x + h.y + h.z + h.w;
            float sq = h.x * h.x + h.y * h.y + h.z * h.z + h.w * h.w;
            #pragma unroll
            for (int o = 16; o >= 1; o >>= 1) {
                s  += __shfl_xor_sync(0xffffffffu, s,  o);
                sq += __shfl_xor_sync(0xffffffffu, sq, o);
            }
            float mu  = s * (1.0f / 128.0f);
            float var = sq * (1.0f / 128.0f) - mu * mu;
            float rs  = rsqrtf(var + 1e-5f);
            if (n < NN) {
                float4 o4;
                o4.x = (h.x - mu) * rs * gv.x + bvv.x;
                o4.y = (h.y - mu) * rs * gv.y + bvv.y;
                o4.z = (h.z - mu) * rs * gv.z + bvv.z;
                o4.w = (h.w - mu) * rs * gv.w + bvv.w;
                ((float4*)out)[(size_t)n * 32 + lane] = o4;
            }
        }
        __syncthreads();
        cur ^= 1;
    }
}

// ---------------------------------------------------------------------------
extern "C" void kernel_launch(void* const* d_in, const int* in_sizes, int n_in,
                              void* d_out, int out_size) {
    const float* x     = (const float*)d_in[0];
    const float* eh_in = (const float*)d_in[1];
    const float* et_in = (const float*)d_in[2];
    const int*   tidx  = (const int*)  d_in[3];
    const float* tw    = (const float*)d_in[4];
    const float* Wh    = (const float*)d_in[5];
    const float* bh    = (const float*)d_in[6];
    const float* Wt    = (const float*)d_in[7];
    const float* bt    = (const float*)d_in[8];
    const float* W1    = (const float*)d_in[9];
    const float* b1    = (const float*)d_in[10];
    const float* W2    = (const float*)d_in[11];
    const float* b2    = (const float*)d_in[12];
    const float* gamma = (const float*)d_in[13];
    const float* beta  = (const float*)d_in[14];
    float* out = (float*)d_out;

    cudaFuncSetAttribute(k1_proj, cudaFuncAttributeMaxDynamicSharedMemorySize, K1_SMEM);
    cudaFuncSetAttribute(k3_out,  cudaFuncAttributeMaxDynamicSharedMemorySize, K3_SMEM);

    k1_proj<<<NSM * 2, 256, K1_SMEM>>>(eh_in, et_in, Wh, bh, Wt, bt);
    k2_attn<<<NTILES, 256>>>(x, tidx, tw);
    k3_out<<<NSM, 256, K3_SMEM>>>(W1, b1, W2, b2, gamma, beta, out);
}